// round 2
// baseline (speedup 1.0000x reference)
#include <cuda_runtime.h>
#include <mma.h>
#include <cmath>

using namespace nvcuda;

constexpr int kB = 4, kS = 2048, kD = 1024, kH = 16, kHD = 64, kFF = 4096;
constexpr int kM = kB * kS;          // 8192 rows
constexpr int kQKV = 3 * kD;         // 3072

// ---------------- scratch (static device globals; no allocation) ----------------
__device__ float g_h1[(size_t)kM * kD];       // ln1 out, reused as ln2 out
__device__ float g_wqkv[(size_t)kD * kQKV];   // packed QKV weight (D x 3D)
__device__ float g_bqkv[kQKV];                // packed QKV bias
__device__ float g_qkv[(size_t)kM * kQKV];    // q|k|v, layout [b,s, 3*D] with head-concat cols
__device__ float g_attn[(size_t)kM * kD];     // attention output (concat heads)
__device__ float g_x2[(size_t)kM * kD];       // residual after attention
__device__ float g_ff1[(size_t)kM * kFF];     // FFN hidden

// ---------------- weight/bias packing ----------------
__global__ void pack_qkv_kernel(const float* __restrict__ Wq, const float* __restrict__ Wk,
                                const float* __restrict__ Wv, const float* __restrict__ bq,
                                const float* __restrict__ bk, const float* __restrict__ bv)
{
    int idx = blockIdx.x * blockDim.x + threadIdx.x;
    const int total = kD * kQKV;
    if (idx >= total) return;
    int d = idx / kQKV;
    int n = idx % kQKV;
    int sect = n / kD;
    int c = n % kD;
    int h = c / kHD;
    int e = c % kHD;
    const float* W = (sect == 0) ? Wq : (sect == 1) ? Wk : Wv;
    g_wqkv[idx] = W[((size_t)h * kD + d) * kHD + e];
    if (idx < kQKV) {
        const float* bb = (idx < kD) ? bq : (idx < 2 * kD) ? bk : bv;
        g_bqkv[idx] = bb[idx % kD];
    }
}

// ---------------- LayerNorm (one block per row, D=1024) ----------------
__global__ void ln_kernel(const float* __restrict__ x, const float* __restrict__ g,
                          const float* __restrict__ beta, float* __restrict__ o)
{
    __shared__ float red[8];
    int row = blockIdx.x;
    int t = threadIdx.x;  // 256
    float4 v = reinterpret_cast<const float4*>(x + (size_t)row * kD)[t];
    float s = v.x + v.y + v.z + v.w;
#pragma unroll
    for (int off = 16; off; off >>= 1) s += __shfl_xor_sync(0xffffffffu, s, off);
    if ((t & 31) == 0) red[t >> 5] = s;
    __syncthreads();
    float tot = 0.f;
#pragma unroll
    for (int i = 0; i < 8; i++) tot += red[i];
    float mu = tot * (1.0f / kD);
    __syncthreads();
    float d0 = v.x - mu, d1 = v.y - mu, d2 = v.z - mu, d3 = v.w - mu;
    float s2 = d0 * d0 + d1 * d1 + d2 * d2 + d3 * d3;
#pragma unroll
    for (int off = 16; off; off >>= 1) s2 += __shfl_xor_sync(0xffffffffu, s2, off);
    if ((t & 31) == 0) red[t >> 5] = s2;
    __syncthreads();
    float tot2 = 0.f;
#pragma unroll
    for (int i = 0; i < 8; i++) tot2 += red[i];
    float inv = rsqrtf(tot2 * (1.0f / kD) + 1e-5f);
    float4 gg = reinterpret_cast<const float4*>(g)[t];
    float4 bb = reinterpret_cast<const float4*>(beta)[t];
    float4 r;
    r.x = d0 * inv * gg.x + bb.x;
    r.y = d1 * inv * gg.y + bb.y;
    r.z = d2 * inv * gg.z + bb.z;
    r.w = d3 * inv * gg.w + bb.w;
    reinterpret_cast<float4*>(o + (size_t)row * kD)[t] = r;
}

// ---------------- TF32 WMMA GEMM: C[M,N] = A[M,K] @ B[K,N] (row-major) ----------------
constexpr int GBM = 128, GBN = 128, GBK = 32;
constexpr int A_LD = 40;    // GBK + 8 (32B-multiple row stride)
constexpr int B_LD = 136;   // GBN + 8

__global__ __launch_bounds__(256) void gemm_tf32(const float* __restrict__ A,
                                                 const float* __restrict__ Bm,
                                                 float* __restrict__ C,
                                                 int M, int N, int K)
{
    __shared__ float As[GBM * A_LD];
    __shared__ float Bs[GBK * B_LD];

    const int bm = blockIdx.y * GBM;
    const int bn = blockIdx.x * GBN;
    const int t = threadIdx.x;
    const int warp = t >> 5;
    const int wm = warp >> 2;   // 0..1  -> 64 rows each
    const int wn = warp & 3;    // 0..3  -> 32 cols each

    wmma::fragment<wmma::accumulator, 16, 16, 8, float> acc[4][2];
#pragma unroll
    for (int i = 0; i < 4; i++)
#pragma unroll
        for (int j = 0; j < 2; j++) wmma::fill_fragment(acc[i][j], 0.0f);

    for (int k0 = 0; k0 < K; k0 += GBK) {
#pragma unroll
        for (int i = 0; i < 4; i++) {
            int idx = t + i * 256;           // 0..1023
            int r = idx >> 3;                // 0..127
            int c = (idx & 7) << 2;          // 0..28
            float4 v = *reinterpret_cast<const float4*>(A + (size_t)(bm + r) * K + k0 + c);
            *reinterpret_cast<float4*>(&As[r * A_LD + c]) = v;
        }
#pragma unroll
        for (int i = 0; i < 4; i++) {
            int idx = t + i * 256;
            int r = idx >> 5;                // 0..31
            int c = (idx & 31) << 2;         // 0..124
            float4 v = *reinterpret_cast<const float4*>(Bm + (size_t)(k0 + r) * N + bn + c);
            *reinterpret_cast<float4*>(&Bs[r * B_LD + c]) = v;
        }
        __syncthreads();

#pragma unroll
        for (int kk = 0; kk < 4; kk++) {
            wmma::fragment<wmma::matrix_a, 16, 16, 8, wmma::precision::tf32, wmma::row_major> af[4];
            wmma::fragment<wmma::matrix_b, 16, 16, 8, wmma::precision::tf32, wmma::row_major> bf[2];
#pragma unroll
            for (int i = 0; i < 4; i++) {
                wmma::load_matrix_sync(af[i], &As[(wm * 64 + i * 16) * A_LD + kk * 8], A_LD);
#pragma unroll
                for (int e = 0; e < af[i].num_elements; e++)
                    af[i].x[e] = wmma::__float_to_tf32(af[i].x[e]);
            }
#pragma unroll
            for (int j = 0; j < 2; j++) {
                wmma::load_matrix_sync(bf[j], &Bs[(kk * 8) * B_LD + wn * 32 + j * 16], B_LD);
#pragma unroll
                for (int e = 0; e < bf[j].num_elements; e++)
                    bf[j].x[e] = wmma::__float_to_tf32(bf[j].x[e]);
            }
#pragma unroll
            for (int i = 0; i < 4; i++)
#pragma unroll
                for (int j = 0; j < 2; j++)
                    wmma::mma_sync(acc[i][j], af[i], bf[j], acc[i][j]);
        }
        __syncthreads();
    }

#pragma unroll
    for (int i = 0; i < 4; i++)
#pragma unroll
        for (int j = 0; j < 2; j++)
            wmma::store_matrix_sync(C + (size_t)(bm + wm * 64 + i * 16) * N + bn + wn * 32 + j * 16,
                                    acc[i][j], N, wmma::mem_row_major);
}

// ---------------- fused elementwise epilogues ----------------
// mode 0: C += bias
// mode 1: C = C + bias + res
// mode 2: C = gelu(C + bias)
// mode 3: C = gelu(C + bias) + res
__device__ __forceinline__ float gelu_exact(float x)
{
    return 0.5f * x * (1.0f + erff(x * 0.70710678118654752f));
}

__global__ void ep_kernel(float* __restrict__ C, const float* __restrict__ bias,
                          const float* __restrict__ res, int total4, int cols4, int mode)
{
    int i = blockIdx.x * blockDim.x + threadIdx.x;
    if (i >= total4) return;
    float4 c = reinterpret_cast<float4*>(C)[i];
    float4 bb = reinterpret_cast<const float4*>(bias)[i % cols4];
    c.x += bb.x; c.y += bb.y; c.z += bb.z; c.w += bb.w;
    if (mode >= 2) {
        c.x = gelu_exact(c.x); c.y = gelu_exact(c.y);
        c.z = gelu_exact(c.z); c.w = gelu_exact(c.w);
    }
    if (mode == 1 || mode == 3) {
        float4 r = reinterpret_cast<const float4*>(res)[i];
        c.x += r.x; c.y += r.y; c.z += r.z; c.w += r.w;
    }
    reinterpret_cast<float4*>(C)[i] = c;
}

// ---------------- flash attention (fp32, causal) ----------------
constexpr int AQ = 64;      // query tile = key tile
constexpr int ALD = 65;     // padded smem stride

__global__ __launch_bounds__(256) void attn_kernel(const float* __restrict__ qkv,
                                                   float* __restrict__ out)
{
    extern __shared__ float sm[];
    float* Qs = sm;                  // [64][65]
    float* Ks = sm + AQ * ALD;       // [64][65], reused for P
    float* Vs = sm + 2 * AQ * ALD;   // [64][65]

    const int qb = blockIdx.x;       // 0..31
    const int bh = blockIdx.y;       // 0..63
    const int b = bh >> 4;
    const int h = bh & 15;
    const int t = threadIdx.x;

    const float* base = qkv + (size_t)b * kS * kQKV + h * kHD;

    // load Q tile (pre-scaled by 1/sqrt(HD) = 0.125)
#pragma unroll
    for (int i = 0; i < 4; i++) {
        int idx = t + i * 256;
        int r = idx >> 4;
        int c = (idx & 15) << 2;
        float4 v = *reinterpret_cast<const float4*>(base + (size_t)(qb * AQ + r) * kQKV + c);
        float* dst = &Qs[r * ALD + c];
        dst[0] = v.x * 0.125f; dst[1] = v.y * 0.125f;
        dst[2] = v.z * 0.125f; dst[3] = v.w * 0.125f;
    }

    const int qr0 = (t >> 4) << 2;   // 4 query rows
    const int c0  = (t & 15) << 2;   // 4 key cols / 4 output dims

    float o[4][4];
    float m[4], l[4];
#pragma unroll
    for (int i = 0; i < 4; i++) {
        m[i] = -1e30f; l[i] = 0.f;
#pragma unroll
        for (int j = 0; j < 4; j++) o[i][j] = 0.f;
    }

    for (int jb = 0; jb <= qb; jb++) {
        __syncthreads();   // previous iteration done with Ks(P)/Vs (also orders Qs on iter 0)
#pragma unroll
        for (int i = 0; i < 4; i++) {
            int idx = t + i * 256;
            int r = idx >> 4;
            int c = (idx & 15) << 2;
            const float* kr = base + (size_t)(jb * AQ + r) * kQKV + kD + c;
            float4 kv = *reinterpret_cast<const float4*>(kr);
            float4 vv = *reinterpret_cast<const float4*>(kr + kD);
            float* kd = &Ks[r * ALD + c];
            kd[0] = kv.x; kd[1] = kv.y; kd[2] = kv.z; kd[3] = kv.w;
            float* vd = &Vs[r * ALD + c];
            vd[0] = vv.x; vd[1] = vv.y; vd[2] = vv.z; vd[3] = vv.w;
        }
        __syncthreads();

        float s[4][4];
#pragma unroll
        for (int i = 0; i < 4; i++)
#pragma unroll
            for (int j = 0; j < 4; j++) s[i][j] = 0.f;

#pragma unroll 8
        for (int d = 0; d < kHD; d++) {
            float qv[4], kv[4];
#pragma unroll
            for (int i = 0; i < 4; i++) qv[i] = Qs[(qr0 + i) * ALD + d];
#pragma unroll
            for (int j = 0; j < 4; j++) kv[j] = Ks[(c0 + j) * ALD + d];
#pragma unroll
            for (int i = 0; i < 4; i++)
#pragma unroll
                for (int j = 0; j < 4; j++) s[i][j] += qv[i] * kv[j];
        }

        if (jb == qb) {
#pragma unroll
            for (int i = 0; i < 4; i++)
#pragma unroll
                for (int j = 0; j < 4; j++)
                    if (c0 + j > qr0 + i) s[i][j] = -1e30f;
        }

        float p[4][4];
#pragma unroll
        for (int i = 0; i < 4; i++) {
            float mx = fmaxf(fmaxf(s[i][0], s[i][1]), fmaxf(s[i][2], s[i][3]));
#pragma unroll
            for (int off = 1; off < 16; off <<= 1)
                mx = fmaxf(mx, __shfl_xor_sync(0xffffffffu, mx, off));
            float mn = fmaxf(m[i], mx);
            float a = __expf(m[i] - mn);
            float rs = 0.f;
#pragma unroll
            for (int j = 0; j < 4; j++) {
                p[i][j] = __expf(s[i][j] - mn);
                rs += p[i][j];
            }
#pragma unroll
            for (int off = 1; off < 16; off <<= 1)
                rs += __shfl_xor_sync(0xffffffffu, rs, off);
            l[i] = l[i] * a + rs;
            m[i] = mn;
#pragma unroll
            for (int j = 0; j < 4; j++) o[i][j] *= a;
        }

        __syncthreads();   // everyone finished reading Ks for scores
#pragma unroll
        for (int i = 0; i < 4; i++)
#pragma unroll
            for (int j = 0; j < 4; j++)
                Ks[(qr0 + i) * ALD + (c0 + j)] = p[i][j];   // P into Ks buffer
        __syncthreads();

#pragma unroll 8
        for (int kc = 0; kc < AQ; kc++) {
            float pv[4], vv[4];
#pragma unroll
            for (int i = 0; i < 4; i++) pv[i] = Ks[(qr0 + i) * ALD + kc];
#pragma unroll
            for (int j = 0; j < 4; j++) vv[j] = Vs[kc * ALD + c0 + j];
#pragma unroll
            for (int i = 0; i < 4; i++)
#pragma unroll
                for (int j = 0; j < 4; j++) o[i][j] += pv[i] * vv[j];
        }
    }

#pragma unroll
    for (int i = 0; i < 4; i++) {
        float inv = 1.0f / l[i];
        int row = qb * AQ + qr0 + i;
        float4 r;
        r.x = o[i][0] * inv; r.y = o[i][1] * inv;
        r.z = o[i][2] * inv; r.w = o[i][3] * inv;
        *reinterpret_cast<float4*>(out + ((size_t)(b * kS + row)) * kD + h * kHD + c0) = r;
    }
}

// ---------------- launch ----------------
extern "C" void kernel_launch(void* const* d_in, const int* in_sizes, int n_in,
                              void* d_out, int out_size)
{
    const float* x    = (const float*)d_in[0];
    const float* Wq   = (const float*)d_in[1];
    const float* bq   = (const float*)d_in[2];
    const float* Wk   = (const float*)d_in[3];
    const float* bk   = (const float*)d_in[4];
    const float* Wv   = (const float*)d_in[5];
    const float* bv   = (const float*)d_in[6];
    const float* Wo   = (const float*)d_in[7];
    const float* bo   = (const float*)d_in[8];
    const float* W1   = (const float*)d_in[9];
    const float* b1   = (const float*)d_in[10];
    const float* W2   = (const float*)d_in[11];
    const float* b2   = (const float*)d_in[12];
    const float* ln1g = (const float*)d_in[13];
    const float* ln1b = (const float*)d_in[14];
    const float* ln2g = (const float*)d_in[15];
    const float* ln2b = (const float*)d_in[16];
    float* out = (float*)d_out;

    float *h1, *wqkv, *bqkv, *qkv, *attn, *x2, *ff1;
    cudaGetSymbolAddress((void**)&h1,   g_h1);
    cudaGetSymbolAddress((void**)&wqkv, g_wqkv);
    cudaGetSymbolAddress((void**)&bqkv, g_bqkv);
    cudaGetSymbolAddress((void**)&qkv,  g_qkv);
    cudaGetSymbolAddress((void**)&attn, g_attn);
    cudaGetSymbolAddress((void**)&x2,   g_x2);
    cudaGetSymbolAddress((void**)&ff1,  g_ff1);

    const int attn_smem = 3 * AQ * ALD * (int)sizeof(float);   // 49920
    cudaFuncSetAttribute(attn_kernel, cudaFuncAttributeMaxDynamicSharedMemorySize, attn_smem);

    // 1. pack QKV weights/biases
    pack_qkv_kernel<<<(kD * kQKV + 255) / 256, 256>>>(Wq, Wk, Wv, bq, bk, bv);
    // 2. LN1
    ln_kernel<<<kM, 256>>>(x, ln1g, ln1b, h1);
    // 3. QKV projection
    gemm_tf32<<<dim3(kQKV / GBN, kM / GBM), 256>>>(h1, wqkv, qkv, kM, kQKV, kD);
    ep_kernel<<<(kM * kQKV / 4 + 255) / 256, 256>>>(qkv, bqkv, nullptr, kM * kQKV / 4, kQKV / 4, 0);
    // 4. attention
    attn_kernel<<<dim3(kS / AQ, kB * kH), 256, attn_smem>>>(qkv, attn);
    // 5. output projection + residual
    gemm_tf32<<<dim3(kD / GBN, kM / GBM), 256>>>(attn, Wo, x2, kM, kD, kD);
    ep_kernel<<<(kM * kD / 4 + 255) / 256, 256>>>(x2, bo, x, kM * kD / 4, kD / 4, 1);
    // 6. LN2
    ln_kernel<<<kM, 256>>>(x2, ln2g, ln2b, h1);
    // 7. FFN up + GELU
    gemm_tf32<<<dim3(kFF / GBN, kM / GBM), 256>>>(h1, W1, ff1, kM, kFF, kD);
    ep_kernel<<<(kM * kFF / 4 + 255) / 256, 256>>>(ff1, b1, nullptr, kM * kFF / 4, kFF / 4, 2);
    // 8. FFN down + GELU + residual -> out
    gemm_tf32<<<dim3(kD / GBN, kM / GBM), 256>>>(ff1, W2, out, kM, kD, kFF);
    ep_kernel<<<(kM * kD / 4 + 255) / 256, 256>>>(out, b2, x2, kM * kD / 4, kD / 4, 3);
}

// round 4
// speedup vs baseline: 1.1697x; 1.1697x over previous
#include <cuda_runtime.h>
#include <mma.h>
#include <cmath>
#include <cstdint>

using namespace nvcuda;

constexpr int kB = 4, kS = 2048, kD = 1024, kH = 16, kHD = 64, kFF = 4096;
constexpr int kM = kB * kS;          // 8192 rows
constexpr int kQKV = 3 * kD;         // 3072

// ---------------- scratch (static device globals; no allocation) ----------------
__device__ float g_h1[(size_t)kM * kD];
__device__ float g_wqkv[(size_t)kD * kQKV];
__device__ float g_bqkv[kQKV];
__device__ float g_qkv[(size_t)kM * kQKV];
__device__ float g_attn[(size_t)kM * kD];
__device__ float g_x2[(size_t)kM * kD];
__device__ float g_ff1[(size_t)kM * kFF];

// ---------------- weight/bias packing ----------------
__global__ void pack_qkv_kernel(const float* __restrict__ Wq, const float* __restrict__ Wk,
                                const float* __restrict__ Wv, const float* __restrict__ bq,
                                const float* __restrict__ bk, const float* __restrict__ bv)
{
    int idx = blockIdx.x * blockDim.x + threadIdx.x;
    const int total = kD * kQKV;
    if (idx >= total) return;
    int d = idx / kQKV;
    int n = idx % kQKV;
    int sect = n / kD;
    int c = n % kD;
    int h = c / kHD;
    int e = c % kHD;
    const float* W = (sect == 0) ? Wq : (sect == 1) ? Wk : Wv;
    g_wqkv[idx] = W[((size_t)h * kD + d) * kHD + e];
    if (idx < kQKV) {
        const float* bb = (idx < kD) ? bq : (idx < 2 * kD) ? bk : bv;
        g_bqkv[idx] = bb[idx % kD];
    }
}

// ---------------- LayerNorm (one block per row, D=1024) ----------------
__global__ void ln_kernel(const float* __restrict__ x, const float* __restrict__ g,
                          const float* __restrict__ beta, float* __restrict__ o)
{
    __shared__ float red[8];
    int row = blockIdx.x;
    int t = threadIdx.x;  // 256
    float4 v = reinterpret_cast<const float4*>(x + (size_t)row * kD)[t];
    float s = v.x + v.y + v.z + v.w;
#pragma unroll
    for (int off = 16; off; off >>= 1) s += __shfl_xor_sync(0xffffffffu, s, off);
    if ((t & 31) == 0) red[t >> 5] = s;
    __syncthreads();
    float tot = 0.f;
#pragma unroll
    for (int i = 0; i < 8; i++) tot += red[i];
    float mu = tot * (1.0f / kD);
    __syncthreads();
    float d0 = v.x - mu, d1 = v.y - mu, d2 = v.z - mu, d3 = v.w - mu;
    float s2 = d0 * d0 + d1 * d1 + d2 * d2 + d3 * d3;
#pragma unroll
    for (int off = 16; off; off >>= 1) s2 += __shfl_xor_sync(0xffffffffu, s2, off);
    if ((t & 31) == 0) red[t >> 5] = s2;
    __syncthreads();
    float tot2 = 0.f;
#pragma unroll
    for (int i = 0; i < 8; i++) tot2 += red[i];
    float inv = rsqrtf(tot2 * (1.0f / kD) + 1e-5f);
    float4 gg = reinterpret_cast<const float4*>(g)[t];
    float4 bb = reinterpret_cast<const float4*>(beta)[t];
    float4 r;
    r.x = d0 * inv * gg.x + bb.x;
    r.y = d1 * inv * gg.y + bb.y;
    r.z = d2 * inv * gg.z + bb.z;
    r.w = d3 * inv * gg.w + bb.w;
    reinterpret_cast<float4*>(o + (size_t)row * kD)[t] = r;
}

// ---------------- helpers ----------------
__device__ __forceinline__ void cp_async16(void* smem, const void* gmem)
{
    unsigned int s = (unsigned int)__cvta_generic_to_shared(smem);
    asm volatile("cp.async.cg.shared.global [%0], [%1], 16;\n" :: "r"(s), "l"(gmem));
}

__device__ __forceinline__ float gelu_exact(float x)
{
    return 0.5f * x * (1.0f + erff(x * 0.70710678118654752f));
}

// ---------------- TF32 WMMA GEMM, cp.async double-buffered, fused epilogue ----------------
// C[M,N] = A[M,K] @ B[K,N]  then:
// mode 0: C = C + bias
// mode 1: C = C + bias + res
// mode 2: C = gelu(C + bias)
// mode 3: C = gelu(C + bias) + res
constexpr int GBM = 128, GBN = 128, GBK = 32;
constexpr int A_LD = 40;    // GBK + 8
constexpr int B_LD = 136;   // GBN + 8
constexpr int C_LD = 136;
constexpr int ASZ = GBM * A_LD;   // 5120 floats
constexpr int BSZ = GBK * B_LD;   // 4352 floats
constexpr int GEMM_SMEM = (2 * ASZ + 2 * BSZ) * 4;   // 75776 bytes (C stage: 128*136*4=69632 fits)

__global__ __launch_bounds__(256) void gemm_tf32(const float* __restrict__ A,
                                                 const float* __restrict__ Bm,
                                                 float* __restrict__ C,
                                                 const float* __restrict__ bias,
                                                 const float* __restrict__ res,
                                                 int M, int N, int K, int mode)
{
    extern __shared__ float sm[];
    float* As = sm;               // [2][ASZ]
    float* Bs = sm + 2 * ASZ;     // [2][BSZ]

    const int bm = blockIdx.y * GBM;
    const int bn = blockIdx.x * GBN;
    const int t = threadIdx.x;
    const int warp = t >> 5;
    const int wm = warp >> 2;   // 0..1 -> 64 rows
    const int wn = warp & 3;    // 0..3 -> 32 cols

    wmma::fragment<wmma::accumulator, 16, 16, 8, float> acc[4][2];
#pragma unroll
    for (int i = 0; i < 4; i++)
#pragma unroll
        for (int j = 0; j < 2; j++) wmma::fill_fragment(acc[i][j], 0.0f);

    // per-thread load coordinates
    const int ar = t >> 3;             // 0..31 (x4 rows via +32)
    const int ac = (t & 7) << 2;       // 0..28
    const int br = t >> 5;             // 0..7  (x4 rows via +8)
    const int bc = (t & 31) << 2;      // 0..124

    const int KT = K / GBK;

    auto load_tile = [&](int kt, int buf) {
        const float* Ab = A + (size_t)bm * K + (size_t)kt * GBK;
        const float* Bb = Bm + (size_t)kt * GBK * N + bn;
#pragma unroll
        for (int i = 0; i < 4; i++) {
            int r = ar + i * 32;
            cp_async16(&As[buf * ASZ + r * A_LD + ac], Ab + (size_t)r * K + ac);
        }
#pragma unroll
        for (int i = 0; i < 4; i++) {
            int r = br + i * 8;
            cp_async16(&Bs[buf * BSZ + r * B_LD + bc], Bb + (size_t)r * N + bc);
        }
        asm volatile("cp.async.commit_group;\n");
    };

    load_tile(0, 0);

    for (int kt = 0; kt < KT; kt++) {
        const int buf = kt & 1;
        if (kt + 1 < KT) {
            load_tile(kt + 1, buf ^ 1);
            asm volatile("cp.async.wait_group 1;\n");
        } else {
            asm volatile("cp.async.wait_group 0;\n");
        }
        __syncthreads();

        const float* Ab = &As[buf * ASZ];
#pragma unroll
        for (int kk = 0; kk < 4; kk++) {
            wmma::fragment<wmma::matrix_a, 16, 16, 8, wmma::precision::tf32, wmma::row_major> af[4];
            wmma::fragment<wmma::matrix_b, 16, 16, 8, wmma::precision::tf32, wmma::row_major> bf[2];
#pragma unroll
            for (int i = 0; i < 4; i++) {
                wmma::load_matrix_sync(af[i], &Ab[(wm * 64 + i * 16) * A_LD + kk * 8], A_LD);
#pragma unroll
                for (int e = 0; e < af[i].num_elements; e++)
                    af[i].x[e] = wmma::__float_to_tf32(af[i].x[e]);
            }
#pragma unroll
            for (int j = 0; j < 2; j++) {
                wmma::load_matrix_sync(bf[j], &Bs[buf * BSZ + (kk * 8) * B_LD + wn * 32 + j * 16], B_LD);
#pragma unroll
                for (int e = 0; e < bf[j].num_elements; e++)
                    bf[j].x[e] = wmma::__float_to_tf32(bf[j].x[e]);
            }
#pragma unroll
            for (int i = 0; i < 4; i++)
#pragma unroll
                for (int j = 0; j < 2; j++)
                    wmma::mma_sync(acc[i][j], af[i], bf[j], acc[i][j]);
        }
        __syncthreads();
    }

    // ---- fused epilogue: stage C tile in smem, apply bias/gelu/res, write out ----
    float* Cs = sm;   // reuse (all compute done; last loop iteration ended with syncthreads)
#pragma unroll
    for (int i = 0; i < 4; i++)
#pragma unroll
        for (int j = 0; j < 2; j++)
            wmma::store_matrix_sync(&Cs[(wm * 64 + i * 16) * C_LD + wn * 32 + j * 16],
                                    acc[i][j], C_LD, wmma::mem_row_major);
    __syncthreads();

#pragma unroll
    for (int i = 0; i < 16; i++) {
        int idx = t + i * 256;        // 0..4095 float4 slots
        int r = idx >> 5;             // 0..127
        int c4 = (idx & 31) << 2;     // 0..124
        float* src = &Cs[r * C_LD + c4];
        float4 c = make_float4(src[0], src[1], src[2], src[3]);
        float4 bb = *reinterpret_cast<const float4*>(bias + bn + c4);
        c.x += bb.x; c.y += bb.y; c.z += bb.z; c.w += bb.w;
        if (mode >= 2) {
            c.x = gelu_exact(c.x); c.y = gelu_exact(c.y);
            c.z = gelu_exact(c.z); c.w = gelu_exact(c.w);
        }
        if (mode == 1 || mode == 3) {
            float4 rr = *reinterpret_cast<const float4*>(res + (size_t)(bm + r) * N + bn + c4);
            c.x += rr.x; c.y += rr.y; c.z += rr.z; c.w += rr.w;
        }
        *reinterpret_cast<float4*>(C + (size_t)(bm + r) * N + bn + c4) = c;
    }
}

// ---------------- flash attention (fp32, causal) ----------------
constexpr int AQ = 64;
constexpr int ALD = 65;

__global__ __launch_bounds__(256) void attn_kernel(const float* __restrict__ qkv,
                                                   float* __restrict__ out)
{
    extern __shared__ float sm[];
    float* Qs = sm;
    float* Ks = sm + AQ * ALD;
    float* Vs = sm + 2 * AQ * ALD;

    const int qb = blockIdx.x;
    const int bh = blockIdx.y;
    const int b = bh >> 4;
    const int h = bh & 15;
    const int t = threadIdx.x;

    const float* base = qkv + (size_t)b * kS * kQKV + h * kHD;

#pragma unroll
    for (int i = 0; i < 4; i++) {
        int idx = t + i * 256;
        int r = idx >> 4;
        int c = (idx & 15) << 2;
        float4 v = *reinterpret_cast<const float4*>(base + (size_t)(qb * AQ + r) * kQKV + c);
        float* dst = &Qs[r * ALD + c];
        dst[0] = v.x * 0.125f; dst[1] = v.y * 0.125f;
        dst[2] = v.z * 0.125f; dst[3] = v.w * 0.125f;
    }

    const int qr0 = (t >> 4) << 2;
    const int c0  = (t & 15) << 2;

    float o[4][4];
    float m[4], l[4];
#pragma unroll
    for (int i = 0; i < 4; i++) {
        m[i] = -1e30f; l[i] = 0.f;
#pragma unroll
        for (int j = 0; j < 4; j++) o[i][j] = 0.f;
    }

    for (int jb = 0; jb <= qb; jb++) {
        __syncthreads();
#pragma unroll
        for (int i = 0; i < 4; i++) {
            int idx = t + i * 256;
            int r = idx >> 4;
            int c = (idx & 15) << 2;
            const float* kr = base + (size_t)(jb * AQ + r) * kQKV + kD + c;
            float4 kv = *reinterpret_cast<const float4*>(kr);
            float4 vv = *reinterpret_cast<const float4*>(kr + kD);
            float* kd = &Ks[r * ALD + c];
            kd[0] = kv.x; kd[1] = kv.y; kd[2] = kv.z; kd[3] = kv.w;
            float* vd = &Vs[r * ALD + c];
            vd[0] = vv.x; vd[1] = vv.y; vd[2] = vv.z; vd[3] = vv.w;
        }
        __syncthreads();

        float s[4][4];
#pragma unroll
        for (int i = 0; i < 4; i++)
#pragma unroll
            for (int j = 0; j < 4; j++) s[i][j] = 0.f;

#pragma unroll 8
        for (int d = 0; d < kHD; d++) {
            float qv[4], kv[4];
#pragma unroll
            for (int i = 0; i < 4; i++) qv[i] = Qs[(qr0 + i) * ALD + d];
#pragma unroll
            for (int j = 0; j < 4; j++) kv[j] = Ks[(c0 + j) * ALD + d];
#pragma unroll
            for (int i = 0; i < 4; i++)
#pragma unroll
                for (int j = 0; j < 4; j++) s[i][j] += qv[i] * kv[j];
        }

        if (jb == qb) {
#pragma unroll
            for (int i = 0; i < 4; i++)
#pragma unroll
                for (int j = 0; j < 4; j++)
                    if (c0 + j > qr0 + i) s[i][j] = -1e30f;
        }

        float p[4][4];
#pragma unroll
        for (int i = 0; i < 4; i++) {
            float mx = fmaxf(fmaxf(s[i][0], s[i][1]), fmaxf(s[i][2], s[i][3]));
#pragma unroll
            for (int off = 1; off < 16; off <<= 1)
                mx = fmaxf(mx, __shfl_xor_sync(0xffffffffu, mx, off));
            float mn = fmaxf(m[i], mx);
            float a = __expf(m[i] - mn);
            float rs = 0.f;
#pragma unroll
            for (int j = 0; j < 4; j++) {
                p[i][j] = __expf(s[i][j] - mn);
                rs += p[i][j];
            }
#pragma unroll
            for (int off = 1; off < 16; off <<= 1)
                rs += __shfl_xor_sync(0xffffffffu, rs, off);
            l[i] = l[i] * a + rs;
            m[i] = mn;
#pragma unroll
            for (int j = 0; j < 4; j++) o[i][j] *= a;
        }

        __syncthreads();
#pragma unroll
        for (int i = 0; i < 4; i++)
#pragma unroll
            for (int j = 0; j < 4; j++)
                Ks[(qr0 + i) * ALD + (c0 + j)] = p[i][j];
        __syncthreads();

#pragma unroll 8
        for (int kc = 0; kc < AQ; kc++) {
            float pv[4], vv[4];
#pragma unroll
            for (int i = 0; i < 4; i++) pv[i] = Ks[(qr0 + i) * ALD + kc];
#pragma unroll
            for (int j = 0; j < 4; j++) vv[j] = Vs[kc * ALD + c0 + j];
#pragma unroll
            for (int i = 0; i < 4; i++)
#pragma unroll
                for (int j = 0; j < 4; j++) o[i][j] += pv[i] * vv[j];
        }
    }

#pragma unroll
    for (int i = 0; i < 4; i++) {
        float inv = 1.0f / l[i];
        int row = qb * AQ + qr0 + i;
        float4 r;
        r.x = o[i][0] * inv; r.y = o[i][1] * inv;
        r.z = o[i][2] * inv; r.w = o[i][3] * inv;
        *reinterpret_cast<float4*>(out + ((size_t)(b * kS + row)) * kD + h * kHD + c0) = r;
    }
}

// ---------------- launch ----------------
extern "C" void kernel_launch(void* const* d_in, const int* in_sizes, int n_in,
                              void* d_out, int out_size)
{
    const float* x    = (const float*)d_in[0];
    const float* Wq   = (const float*)d_in[1];
    const float* bq   = (const float*)d_in[2];
    const float* Wk   = (const float*)d_in[3];
    const float* bk   = (const float*)d_in[4];
    const float* Wv   = (const float*)d_in[5];
    const float* bv   = (const float*)d_in[6];
    const float* Wo   = (const float*)d_in[7];
    const float* bo   = (const float*)d_in[8];
    const float* W1   = (const float*)d_in[9];
    const float* b1   = (const float*)d_in[10];
    const float* W2   = (const float*)d_in[11];
    const float* b2   = (const float*)d_in[12];
    const float* ln1g = (const float*)d_in[13];
    const float* ln1b = (const float*)d_in[14];
    const float* ln2g = (const float*)d_in[15];
    const float* ln2b = (const float*)d_in[16];
    float* out = (float*)d_out;

    float *h1, *wqkv, *bqkv, *qkv, *attn, *x2, *ff1;
    cudaGetSymbolAddress((void**)&h1,   g_h1);
    cudaGetSymbolAddress((void**)&wqkv, g_wqkv);
    cudaGetSymbolAddress((void**)&bqkv, g_bqkv);
    cudaGetSymbolAddress((void**)&qkv,  g_qkv);
    cudaGetSymbolAddress((void**)&attn, g_attn);
    cudaGetSymbolAddress((void**)&x2,   g_x2);
    cudaGetSymbolAddress((void**)&ff1,  g_ff1);

    const int attn_smem = 3 * AQ * ALD * (int)sizeof(float);
    cudaFuncSetAttribute(attn_kernel, cudaFuncAttributeMaxDynamicSharedMemorySize, attn_smem);
    cudaFuncSetAttribute(gemm_tf32, cudaFuncAttributeMaxDynamicSharedMemorySize, GEMM_SMEM);

    // 1. pack QKV weights/biases
    pack_qkv_kernel<<<(kD * kQKV + 255) / 256, 256>>>(Wq, Wk, Wv, bq, bk, bv);
    // 2. LN1
    ln_kernel<<<kM, 256>>>(x, ln1g, ln1b, h1);
    // 3. QKV projection (+bias fused)
    gemm_tf32<<<dim3(kQKV / GBN, kM / GBM), 256, GEMM_SMEM>>>(h1, wqkv, qkv, bqkv, nullptr,
                                                              kM, kQKV, kD, 0);
    // 4. attention
    attn_kernel<<<dim3(kS / AQ, kB * kH), 256, attn_smem>>>(qkv, attn);
    // 5. output projection (+bias+residual fused)
    gemm_tf32<<<dim3(kD / GBN, kM / GBM), 256, GEMM_SMEM>>>(attn, Wo, x2, bo, x,
                                                            kM, kD, kD, 1);
    // 6. LN2
    ln_kernel<<<kM, 256>>>(x2, ln2g, ln2b, h1);
    // 7. FFN up (+bias+gelu fused)
    gemm_tf32<<<dim3(kFF / GBN, kM / GBM), 256, GEMM_SMEM>>>(h1, W1, ff1, b1, nullptr,
                                                             kM, kFF, kD, 2);
    // 8. FFN down (+bias+gelu+residual fused) -> out
    gemm_tf32<<<dim3(kD / GBN, kM / GBM), 256, GEMM_SMEM>>>(ff1, W2, out, b2, x2,
                                                            kM, kD, kFF, 3);
}

// round 5
// speedup vs baseline: 1.2582x; 1.0757x over previous
#include <cuda_runtime.h>
#include <mma.h>
#include <cmath>
#include <cstdint>

using namespace nvcuda;

constexpr int kB = 4, kS = 2048, kD = 1024, kH = 16, kHD = 64, kFF = 4096;
constexpr int kM = kB * kS;          // 8192 rows
constexpr int kQKV = 3 * kD;         // 3072

// ---------------- scratch (static device globals; no allocation) ----------------
__device__ float g_h1[(size_t)kM * kD];
__device__ float g_wqkv[(size_t)kD * kQKV];
__device__ float g_bqkv[kQKV];
__device__ float g_qkv[(size_t)kM * kQKV];
__device__ float g_attn[(size_t)kM * kD];
__device__ float g_x2[(size_t)kM * kD];
__device__ float g_ff1[(size_t)kM * kFF];

// ---------------- weight/bias packing ----------------
__global__ void pack_qkv_kernel(const float* __restrict__ Wq, const float* __restrict__ Wk,
                                const float* __restrict__ Wv, const float* __restrict__ bq,
                                const float* __restrict__ bk, const float* __restrict__ bv)
{
    int idx = blockIdx.x * blockDim.x + threadIdx.x;
    const int total = kD * kQKV;
    if (idx >= total) return;
    int d = idx / kQKV;
    int n = idx % kQKV;
    int sect = n / kD;
    int c = n % kD;
    int h = c / kHD;
    int e = c % kHD;
    const float* W = (sect == 0) ? Wq : (sect == 1) ? Wk : Wv;
    g_wqkv[idx] = W[((size_t)h * kD + d) * kHD + e];
    if (idx < kQKV) {
        const float* bb = (idx < kD) ? bq : (idx < 2 * kD) ? bk : bv;
        g_bqkv[idx] = bb[idx % kD];
    }
}

// ---------------- LayerNorm (one block per row, D=1024) ----------------
__global__ void ln_kernel(const float* __restrict__ x, const float* __restrict__ g,
                          const float* __restrict__ beta, float* __restrict__ o)
{
    __shared__ float red[8];
    int row = blockIdx.x;
    int t = threadIdx.x;  // 256
    float4 v = reinterpret_cast<const float4*>(x + (size_t)row * kD)[t];
    float s = v.x + v.y + v.z + v.w;
#pragma unroll
    for (int off = 16; off; off >>= 1) s += __shfl_xor_sync(0xffffffffu, s, off);
    if ((t & 31) == 0) red[t >> 5] = s;
    __syncthreads();
    float tot = 0.f;
#pragma unroll
    for (int i = 0; i < 8; i++) tot += red[i];
    float mu = tot * (1.0f / kD);
    __syncthreads();
    float d0 = v.x - mu, d1 = v.y - mu, d2 = v.z - mu, d3 = v.w - mu;
    float s2 = d0 * d0 + d1 * d1 + d2 * d2 + d3 * d3;
#pragma unroll
    for (int off = 16; off; off >>= 1) s2 += __shfl_xor_sync(0xffffffffu, s2, off);
    if ((t & 31) == 0) red[t >> 5] = s2;
    __syncthreads();
    float tot2 = 0.f;
#pragma unroll
    for (int i = 0; i < 8; i++) tot2 += red[i];
    float inv = rsqrtf(tot2 * (1.0f / kD) + 1e-5f);
    float4 gg = reinterpret_cast<const float4*>(g)[t];
    float4 bb = reinterpret_cast<const float4*>(beta)[t];
    float4 r;
    r.x = d0 * inv * gg.x + bb.x;
    r.y = d1 * inv * gg.y + bb.y;
    r.z = d2 * inv * gg.z + bb.z;
    r.w = d3 * inv * gg.w + bb.w;
    reinterpret_cast<float4*>(o + (size_t)row * kD)[t] = r;
}

// ---------------- helpers ----------------
__device__ __forceinline__ void cp_async16(void* smem, const void* gmem)
{
    unsigned int s = (unsigned int)__cvta_generic_to_shared(smem);
    asm volatile("cp.async.cg.shared.global [%0], [%1], 16;\n" :: "r"(s), "l"(gmem));
}

__device__ __forceinline__ float gelu_exact(float x)
{
    return 0.5f * x * (1.0f + erff(x * 0.70710678118654752f));
}

// ---------------- TF32 WMMA GEMM, cp.async double-buffered, fused epilogue ----------------
constexpr int GBM = 128, GBN = 128, GBK = 32;
constexpr int A_LD = 40;
constexpr int B_LD = 136;
constexpr int C_LD = 136;
constexpr int ASZ = GBM * A_LD;
constexpr int BSZ = GBK * B_LD;
constexpr int GEMM_SMEM = (2 * ASZ + 2 * BSZ) * 4;

__global__ __launch_bounds__(256) void gemm_tf32(const float* __restrict__ A,
                                                 const float* __restrict__ Bm,
                                                 float* __restrict__ C,
                                                 const float* __restrict__ bias,
                                                 const float* __restrict__ res,
                                                 int M, int N, int K, int mode)
{
    extern __shared__ float sm[];
    float* As = sm;
    float* Bs = sm + 2 * ASZ;

    const int bm = blockIdx.y * GBM;
    const int bn = blockIdx.x * GBN;
    const int t = threadIdx.x;
    const int warp = t >> 5;
    const int wm = warp >> 2;
    const int wn = warp & 3;

    wmma::fragment<wmma::accumulator, 16, 16, 8, float> acc[4][2];
#pragma unroll
    for (int i = 0; i < 4; i++)
#pragma unroll
        for (int j = 0; j < 2; j++) wmma::fill_fragment(acc[i][j], 0.0f);

    const int ar = t >> 3;
    const int ac = (t & 7) << 2;
    const int br = t >> 5;
    const int bc = (t & 31) << 2;

    const int KT = K / GBK;

    auto load_tile = [&](int kt, int buf) {
        const float* Ab = A + (size_t)bm * K + (size_t)kt * GBK;
        const float* Bb = Bm + (size_t)kt * GBK * N + bn;
#pragma unroll
        for (int i = 0; i < 4; i++) {
            int r = ar + i * 32;
            cp_async16(&As[buf * ASZ + r * A_LD + ac], Ab + (size_t)r * K + ac);
        }
#pragma unroll
        for (int i = 0; i < 4; i++) {
            int r = br + i * 8;
            cp_async16(&Bs[buf * BSZ + r * B_LD + bc], Bb + (size_t)r * N + bc);
        }
        asm volatile("cp.async.commit_group;\n");
    };

    load_tile(0, 0);

    for (int kt = 0; kt < KT; kt++) {
        const int buf = kt & 1;
        if (kt + 1 < KT) {
            load_tile(kt + 1, buf ^ 1);
            asm volatile("cp.async.wait_group 1;\n");
        } else {
            asm volatile("cp.async.wait_group 0;\n");
        }
        __syncthreads();

        const float* Ab = &As[buf * ASZ];
#pragma unroll
        for (int kk = 0; kk < 4; kk++) {
            wmma::fragment<wmma::matrix_a, 16, 16, 8, wmma::precision::tf32, wmma::row_major> af[4];
            wmma::fragment<wmma::matrix_b, 16, 16, 8, wmma::precision::tf32, wmma::row_major> bf[2];
#pragma unroll
            for (int i = 0; i < 4; i++) {
                wmma::load_matrix_sync(af[i], &Ab[(wm * 64 + i * 16) * A_LD + kk * 8], A_LD);
#pragma unroll
                for (int e = 0; e < af[i].num_elements; e++)
                    af[i].x[e] = wmma::__float_to_tf32(af[i].x[e]);
            }
#pragma unroll
            for (int j = 0; j < 2; j++) {
                wmma::load_matrix_sync(bf[j], &Bs[buf * BSZ + (kk * 8) * B_LD + wn * 32 + j * 16], B_LD);
#pragma unroll
                for (int e = 0; e < bf[j].num_elements; e++)
                    bf[j].x[e] = wmma::__float_to_tf32(bf[j].x[e]);
            }
#pragma unroll
            for (int i = 0; i < 4; i++)
#pragma unroll
                for (int j = 0; j < 2; j++)
                    wmma::mma_sync(acc[i][j], af[i], bf[j], acc[i][j]);
        }
        __syncthreads();
    }

    float* Cs = sm;
#pragma unroll
    for (int i = 0; i < 4; i++)
#pragma unroll
        for (int j = 0; j < 2; j++)
            wmma::store_matrix_sync(&Cs[(wm * 64 + i * 16) * C_LD + wn * 32 + j * 16],
                                    acc[i][j], C_LD, wmma::mem_row_major);
    __syncthreads();

#pragma unroll
    for (int i = 0; i < 16; i++) {
        int idx = t + i * 256;
        int r = idx >> 5;
        int c4 = (idx & 31) << 2;
        float* src = &Cs[r * C_LD + c4];
        float4 c = make_float4(src[0], src[1], src[2], src[3]);
        float4 bb = *reinterpret_cast<const float4*>(bias + bn + c4);
        c.x += bb.x; c.y += bb.y; c.z += bb.z; c.w += bb.w;
        if (mode >= 2) {
            c.x = gelu_exact(c.x); c.y = gelu_exact(c.y);
            c.z = gelu_exact(c.z); c.w = gelu_exact(c.w);
        }
        if (mode == 1 || mode == 3) {
            float4 rr = *reinterpret_cast<const float4*>(res + (size_t)(bm + r) * N + bn + c4);
            c.x += rr.x; c.y += rr.y; c.z += rr.z; c.w += rr.w;
        }
        *reinterpret_cast<float4*>(C + (size_t)(bm + r) * N + bn + c4) = c;
    }
}

// ---------------- WMMA flash attention (tf32 tensor cores, causal) ----------------
constexpr int SLD = 72;   // 64 + 8 pad
constexpr int ATT_SMEM = (5 * 64 * SLD + 3 * 64) * 4;   // Qs,Ks,Vs,Ss,Os + m,l,a

__global__ __launch_bounds__(256) void attn_kernel(const float* __restrict__ qkv,
                                                   float* __restrict__ out)
{
    extern __shared__ float sm[];
    float* Qs = sm;                     // [64][SLD]
    float* Ks = Qs + 64 * SLD;
    float* Vs = Ks + 64 * SLD;
    float* Ss = Vs + 64 * SLD;          // scores / P / PV temp
    float* Os = Ss + 64 * SLD;          // persistent O accumulator
    float* mrow = Os + 64 * SLD;        // [64]
    float* lrow = mrow + 64;
    float* arow = lrow + 64;

    const int qb = blockIdx.x;          // 0..31
    const int bh = blockIdx.y;          // 0..63
    const int b = bh >> 4;
    const int h = bh & 15;
    const int t = threadIdx.x;
    const int warp = t >> 5;
    const int wq = warp >> 1;           // 0..3 -> q rows 16*wq
    const int wk = warp & 1;            // 0..1 -> cols 32*wk

    const float* base = qkv + (size_t)b * kS * kQKV + h * kHD;

    // load Q (scaled by 1/8), init Os
#pragma unroll
    for (int i = 0; i < 4; i++) {
        int idx = t + i * 256;          // 0..1023
        int r = idx >> 4;
        int c = (idx & 15) << 2;
        float4 v = *reinterpret_cast<const float4*>(base + (size_t)(qb * 64 + r) * kQKV + c);
        float* d = &Qs[r * SLD + c];
        d[0] = v.x * 0.125f; d[1] = v.y * 0.125f;
        d[2] = v.z * 0.125f; d[3] = v.w * 0.125f;
        float* o = &Os[r * SLD + c];
        o[0] = 0.f; o[1] = 0.f; o[2] = 0.f; o[3] = 0.f;
    }
    if (t < 64) { mrow[t] = -1e30f; lrow[t] = 0.f; }

    for (int jb = 0; jb <= qb; jb++) {
        __syncthreads();
        // load K, V tiles
#pragma unroll
        for (int i = 0; i < 4; i++) {
            int idx = t + i * 256;
            int r = idx >> 4;
            int c = (idx & 15) << 2;
            const float* kr = base + (size_t)(jb * 64 + r) * kQKV + kD + c;
            float4 kv = *reinterpret_cast<const float4*>(kr);
            float4 vv = *reinterpret_cast<const float4*>(kr + kD);
            float* kd = &Ks[r * SLD + c];
            kd[0] = kv.x; kd[1] = kv.y; kd[2] = kv.z; kd[3] = kv.w;
            float* vd = &Vs[r * SLD + c];
            vd[0] = vv.x; vd[1] = vv.y; vd[2] = vv.z; vd[3] = vv.w;
        }
        __syncthreads();

        // ---- S = Q @ K^T (warp: 16 q-rows x 32 cols) ----
        {
            wmma::fragment<wmma::accumulator, 16, 16, 8, float> sacc[2];
#pragma unroll
            for (int n = 0; n < 2; n++) wmma::fill_fragment(sacc[n], 0.0f);
#pragma unroll
            for (int kk = 0; kk < 8; kk++) {
                wmma::fragment<wmma::matrix_a, 16, 16, 8, wmma::precision::tf32, wmma::row_major> af;
                wmma::load_matrix_sync(af, &Qs[(wq * 16) * SLD + kk * 8], SLD);
#pragma unroll
                for (int e = 0; e < af.num_elements; e++) af.x[e] = wmma::__float_to_tf32(af.x[e]);
#pragma unroll
                for (int n = 0; n < 2; n++) {
                    wmma::fragment<wmma::matrix_b, 16, 16, 8, wmma::precision::tf32, wmma::col_major> bf;
                    wmma::load_matrix_sync(bf, &Ks[(wk * 32 + n * 16) * SLD + kk * 8], SLD);
#pragma unroll
                    for (int e = 0; e < bf.num_elements; e++) bf.x[e] = wmma::__float_to_tf32(bf.x[e]);
                    wmma::mma_sync(sacc[n], af, bf, sacc[n]);
                }
            }
#pragma unroll
            for (int n = 0; n < 2; n++)
                wmma::store_matrix_sync(&Ss[(wq * 16) * SLD + wk * 32 + n * 16],
                                        sacc[n], SLD, wmma::mem_row_major);
        }
        __syncthreads();

        // ---- online softmax on Ss (4 threads per row, 16 cols each) ----
        {
            const int row = t >> 2;
            const int g = t & 3;
            float* srow = &Ss[row * SLD + g * 16];
            const int gq = qb * 64 + row;
            const int cbase = jb * 64 + g * 16;
            float sv[16];
            float mx = -1e30f;
#pragma unroll
            for (int j = 0; j < 16; j++) {
                float xv = srow[j];
                if (jb == qb && cbase + j > gq) xv = -1e30f;
                sv[j] = xv;
                mx = fmaxf(mx, xv);
            }
            mx = fmaxf(mx, __shfl_xor_sync(0xffffffffu, mx, 1));
            mx = fmaxf(mx, __shfl_xor_sync(0xffffffffu, mx, 2));
            float mold = mrow[row];
            float mn = fmaxf(mold, mx);
            float a = __expf(mold - mn);
            float sum = 0.f;
#pragma unroll
            for (int j = 0; j < 16; j++) {
                float p = __expf(sv[j] - mn);
                srow[j] = p;
                sum += p;
            }
            sum += __shfl_xor_sync(0xffffffffu, sum, 1);
            sum += __shfl_xor_sync(0xffffffffu, sum, 2);
            if (g == 0) {
                mrow[row] = mn;
                lrow[row] = lrow[row] * a + sum;
                arow[row] = a;
            }
        }
        __syncthreads();

        // ---- PV = P @ V (fragments), then Os = a*Os + PV ----
        wmma::fragment<wmma::accumulator, 16, 16, 8, float> oacc[2];
#pragma unroll
        for (int n = 0; n < 2; n++) wmma::fill_fragment(oacc[n], 0.0f);
#pragma unroll
        for (int kk = 0; kk < 8; kk++) {
            wmma::fragment<wmma::matrix_a, 16, 16, 8, wmma::precision::tf32, wmma::row_major> af;
            wmma::load_matrix_sync(af, &Ss[(wq * 16) * SLD + kk * 8], SLD);
#pragma unroll
            for (int e = 0; e < af.num_elements; e++) af.x[e] = wmma::__float_to_tf32(af.x[e]);
#pragma unroll
            for (int n = 0; n < 2; n++) {
                wmma::fragment<wmma::matrix_b, 16, 16, 8, wmma::precision::tf32, wmma::row_major> bf;
                wmma::load_matrix_sync(bf, &Vs[(kk * 8) * SLD + wk * 32 + n * 16], SLD);
#pragma unroll
                for (int e = 0; e < bf.num_elements; e++) bf.x[e] = wmma::__float_to_tf32(bf.x[e]);
                wmma::mma_sync(oacc[n], af, bf, oacc[n]);
            }
        }
        __syncthreads();   // all P reads complete before overwrite
#pragma unroll
        for (int n = 0; n < 2; n++)
            wmma::store_matrix_sync(&Ss[(wq * 16) * SLD + wk * 32 + n * 16],
                                    oacc[n], SLD, wmma::mem_row_major);
        __syncthreads();

#pragma unroll
        for (int i = 0; i < 4; i++) {
            int idx = t + i * 256;
            int r = idx >> 4;
            int c = (idx & 15) << 2;
            float a = arow[r];
            float* od = &Os[r * SLD + c];
            const float* pd = &Ss[r * SLD + c];
            od[0] = od[0] * a + pd[0];
            od[1] = od[1] * a + pd[1];
            od[2] = od[2] * a + pd[2];
            od[3] = od[3] * a + pd[3];
        }
    }
    __syncthreads();

    // write O / l
#pragma unroll
    for (int i = 0; i < 4; i++) {
        int idx = t + i * 256;
        int r = idx >> 4;
        int c = (idx & 15) << 2;
        float inv = 1.0f / lrow[r];
        const float* od = &Os[r * SLD + c];
        float4 v = make_float4(od[0] * inv, od[1] * inv, od[2] * inv, od[3] * inv);
        *reinterpret_cast<float4*>(out + (size_t)(b * kS + qb * 64 + r) * kD + h * kHD + c) = v;
    }
}

// ---------------- launch ----------------
extern "C" void kernel_launch(void* const* d_in, const int* in_sizes, int n_in,
                              void* d_out, int out_size)
{
    const float* x    = (const float*)d_in[0];
    const float* Wq   = (const float*)d_in[1];
    const float* bq   = (const float*)d_in[2];
    const float* Wk   = (const float*)d_in[3];
    const float* bk   = (const float*)d_in[4];
    const float* Wv   = (const float*)d_in[5];
    const float* bv   = (const float*)d_in[6];
    const float* Wo   = (const float*)d_in[7];
    const float* bo   = (const float*)d_in[8];
    const float* W1   = (const float*)d_in[9];
    const float* b1   = (const float*)d_in[10];
    const float* W2   = (const float*)d_in[11];
    const float* b2   = (const float*)d_in[12];
    const float* ln1g = (const float*)d_in[13];
    const float* ln1b = (const float*)d_in[14];
    const float* ln2g = (const float*)d_in[15];
    const float* ln2b = (const float*)d_in[16];
    float* out = (float*)d_out;

    float *h1, *wqkv, *bqkv, *qkv, *attn, *x2, *ff1;
    cudaGetSymbolAddress((void**)&h1,   g_h1);
    cudaGetSymbolAddress((void**)&wqkv, g_wqkv);
    cudaGetSymbolAddress((void**)&bqkv, g_bqkv);
    cudaGetSymbolAddress((void**)&qkv,  g_qkv);
    cudaGetSymbolAddress((void**)&attn, g_attn);
    cudaGetSymbolAddress((void**)&x2,   g_x2);
    cudaGetSymbolAddress((void**)&ff1,  g_ff1);

    cudaFuncSetAttribute(attn_kernel, cudaFuncAttributeMaxDynamicSharedMemorySize, ATT_SMEM);
    cudaFuncSetAttribute(gemm_tf32, cudaFuncAttributeMaxDynamicSharedMemorySize, GEMM_SMEM);

    // 1. pack QKV weights/biases
    pack_qkv_kernel<<<(kD * kQKV + 255) / 256, 256>>>(Wq, Wk, Wv, bq, bk, bv);
    // 2. LN1
    ln_kernel<<<kM, 256>>>(x, ln1g, ln1b, h1);
    // 3. QKV projection (+bias fused)
    gemm_tf32<<<dim3(kQKV / GBN, kM / GBM), 256, GEMM_SMEM>>>(h1, wqkv, qkv, bqkv, nullptr,
                                                              kM, kQKV, kD, 0);
    // 4. attention (tf32 wmma flash)
    attn_kernel<<<dim3(kS / 64, kB * kH), 256, ATT_SMEM>>>(qkv, attn);
    // 5. output projection (+bias+residual fused)
    gemm_tf32<<<dim3(kD / GBN, kM / GBM), 256, GEMM_SMEM>>>(attn, Wo, x2, bo, x,
                                                            kM, kD, kD, 1);
    // 6. LN2
    ln_kernel<<<kM, 256>>>(x2, ln2g, ln2b, h1);
    // 7. FFN up (+bias+gelu fused)
    gemm_tf32<<<dim3(kFF / GBN, kM / GBM), 256, GEMM_SMEM>>>(h1, W1, ff1, b1, nullptr,
                                                             kM, kFF, kD, 2);
    // 8. FFN down (+bias+gelu+residual fused) -> out
    gemm_tf32<<<dim3(kD / GBN, kM / GBM), 256, GEMM_SMEM>>>(ff1, W2, out, b2, x2,
                                                            kM, kD, kFF, 3);
}

// round 6
// speedup vs baseline: 1.3919x; 1.1062x over previous
#include <cuda_runtime.h>
#include <mma.h>
#include <cmath>
#include <cstdint>

using namespace nvcuda;

constexpr int kB = 4, kS = 2048, kD = 1024, kH = 16, kHD = 64, kFF = 4096;
constexpr int kM = kB * kS;          // 8192 rows
constexpr int kQKV = 3 * kD;         // 3072

// ---------------- scratch (static device globals; no allocation) ----------------
__device__ float g_h1[(size_t)kM * kD];
__device__ float g_wqkv[(size_t)kD * kQKV];
__device__ float g_bqkv[kQKV];
__device__ float g_qkv[(size_t)kM * kQKV];
__device__ float g_attn[(size_t)kM * kD];
__device__ float g_x2[(size_t)kM * kD];
__device__ float g_ff1[(size_t)kM * kFF];

// ---------------- weight/bias packing ----------------
__global__ void pack_qkv_kernel(const float* __restrict__ Wq, const float* __restrict__ Wk,
                                const float* __restrict__ Wv, const float* __restrict__ bq,
                                const float* __restrict__ bk, const float* __restrict__ bv)
{
    int idx = blockIdx.x * blockDim.x + threadIdx.x;
    const int total = kD * kQKV;
    if (idx >= total) return;
    int d = idx / kQKV;
    int n = idx % kQKV;
    int sect = n / kD;
    int c = n % kD;
    int h = c / kHD;
    int e = c % kHD;
    const float* W = (sect == 0) ? Wq : (sect == 1) ? Wk : Wv;
    g_wqkv[idx] = W[((size_t)h * kD + d) * kHD + e];
    if (idx < kQKV) {
        const float* bb = (idx < kD) ? bq : (idx < 2 * kD) ? bk : bv;
        g_bqkv[idx] = bb[idx % kD];
    }
}

// ---------------- LayerNorm (one block per row, D=1024) ----------------
__global__ void ln_kernel(const float* __restrict__ x, const float* __restrict__ g,
                          const float* __restrict__ beta, float* __restrict__ o)
{
    __shared__ float red[8];
    int row = blockIdx.x;
    int t = threadIdx.x;  // 256
    float4 v = reinterpret_cast<const float4*>(x + (size_t)row * kD)[t];
    float s = v.x + v.y + v.z + v.w;
#pragma unroll
    for (int off = 16; off; off >>= 1) s += __shfl_xor_sync(0xffffffffu, s, off);
    if ((t & 31) == 0) red[t >> 5] = s;
    __syncthreads();
    float tot = 0.f;
#pragma unroll
    for (int i = 0; i < 8; i++) tot += red[i];
    float mu = tot * (1.0f / kD);
    __syncthreads();
    float d0 = v.x - mu, d1 = v.y - mu, d2 = v.z - mu, d3 = v.w - mu;
    float s2 = d0 * d0 + d1 * d1 + d2 * d2 + d3 * d3;
#pragma unroll
    for (int off = 16; off; off >>= 1) s2 += __shfl_xor_sync(0xffffffffu, s2, off);
    if ((t & 31) == 0) red[t >> 5] = s2;
    __syncthreads();
    float tot2 = 0.f;
#pragma unroll
    for (int i = 0; i < 8; i++) tot2 += red[i];
    float inv = rsqrtf(tot2 * (1.0f / kD) + 1e-5f);
    float4 gg = reinterpret_cast<const float4*>(g)[t];
    float4 bb = reinterpret_cast<const float4*>(beta)[t];
    float4 r;
    r.x = d0 * inv * gg.x + bb.x;
    r.y = d1 * inv * gg.y + bb.y;
    r.z = d2 * inv * gg.z + bb.z;
    r.w = d3 * inv * gg.w + bb.w;
    reinterpret_cast<float4*>(o + (size_t)row * kD)[t] = r;
}

// ---------------- helpers ----------------
__device__ __forceinline__ void cp_async16(void* smem, const void* gmem)
{
    unsigned int s = (unsigned int)__cvta_generic_to_shared(smem);
    asm volatile("cp.async.cg.shared.global [%0], [%1], 16;\n" :: "r"(s), "l"(gmem));
}

__device__ __forceinline__ float gelu_exact(float x)
{
    return 0.5f * x * (1.0f + erff(x * 0.70710678118654752f));
}

// ---------------- TF32 WMMA GEMM: 128x256 block, 64x64 warp, 3-stage cp.async ----------------
constexpr int GBM = 128, GBN = 256, GBK = 32;
constexpr int NSTAGE = 3;
constexpr int A_LD = 40;          // 32 + 8
constexpr int B_LD = 264;         // 256 + 8
constexpr int C_LD = 264;
constexpr int ASZ = GBM * A_LD;   // 5120 floats (20KB)
constexpr int BSZ = GBK * B_LD;   // 8448 floats (33.8KB)
constexpr int STAGE = ASZ + BSZ;  // floats per stage
constexpr int GEMM_SMEM = NSTAGE * STAGE * 4;   // 162816 B; C stage 128*264*4=135168 fits

__global__ __launch_bounds__(256, 1) void gemm_tf32(const float* __restrict__ A,
                                                    const float* __restrict__ Bm,
                                                    float* __restrict__ C,
                                                    const float* __restrict__ bias,
                                                    const float* __restrict__ res,
                                                    int M, int N, int K, int mode)
{
    extern __shared__ float sm[];

    const int bm = blockIdx.y * GBM;
    const int bn = blockIdx.x * GBN;
    const int t = threadIdx.x;
    const int warp = t >> 5;
    const int wm = warp >> 2;   // 0..1 -> 64 rows
    const int wn = warp & 3;    // 0..3 -> 64 cols

    wmma::fragment<wmma::accumulator, 16, 16, 8, float> acc[4][4];
#pragma unroll
    for (int i = 0; i < 4; i++)
#pragma unroll
        for (int j = 0; j < 4; j++) wmma::fill_fragment(acc[i][j], 0.0f);

    // A: 128x32 floats = 1024 float4 -> 4/thread ; B: 32x256 = 2048 float4 -> 8/thread
    const int ar = t >> 3;            // 0..31 (+32*i)
    const int ac = (t & 7) << 2;      // 0..28
    const int br = t >> 6;            // 0..3  (+4*i)
    const int bc = (t & 63) << 2;     // 0..252

    const int KT = K / GBK;

    auto load_tile = [&](int kt, int buf) {
        float* As = sm + buf * STAGE;
        float* Bs = As + ASZ;
        const float* Ab = A + (size_t)bm * K + (size_t)kt * GBK;
        const float* Bb = Bm + (size_t)kt * GBK * N + bn;
#pragma unroll
        for (int i = 0; i < 4; i++) {
            int r = ar + i * 32;
            cp_async16(&As[r * A_LD + ac], Ab + (size_t)r * K + ac);
        }
#pragma unroll
        for (int i = 0; i < 8; i++) {
            int r = br + i * 4;
            cp_async16(&Bs[r * B_LD + bc], Bb + (size_t)r * N + bc);
        }
        asm volatile("cp.async.commit_group;\n");
    };

    load_tile(0, 0);
    load_tile(1, 1);

    for (int kt = 0; kt < KT; kt++) {
        const int buf = kt % NSTAGE;
        if (kt + 2 < KT) {
            load_tile(kt + 2, (kt + 2) % NSTAGE);
            asm volatile("cp.async.wait_group 2;\n");
        } else if (kt + 1 < KT) {
            asm volatile("cp.async.wait_group 1;\n");
        } else {
            asm volatile("cp.async.wait_group 0;\n");
        }
        __syncthreads();

        const float* As = sm + buf * STAGE;
        const float* Bs = As + ASZ;
#pragma unroll
        for (int kk = 0; kk < 4; kk++) {
            wmma::fragment<wmma::matrix_a, 16, 16, 8, wmma::precision::tf32, wmma::row_major> af[4];
            wmma::fragment<wmma::matrix_b, 16, 16, 8, wmma::precision::tf32, wmma::row_major> bf[4];
#pragma unroll
            for (int i = 0; i < 4; i++) {
                wmma::load_matrix_sync(af[i], &As[(wm * 64 + i * 16) * A_LD + kk * 8], A_LD);
#pragma unroll
                for (int e = 0; e < af[i].num_elements; e++)
                    af[i].x[e] = wmma::__float_to_tf32(af[i].x[e]);
            }
#pragma unroll
            for (int j = 0; j < 4; j++) {
                wmma::load_matrix_sync(bf[j], &Bs[(kk * 8) * B_LD + wn * 64 + j * 16], B_LD);
#pragma unroll
                for (int e = 0; e < bf[j].num_elements; e++)
                    bf[j].x[e] = wmma::__float_to_tf32(bf[j].x[e]);
            }
#pragma unroll
            for (int i = 0; i < 4; i++)
#pragma unroll
                for (int j = 0; j < 4; j++)
                    wmma::mma_sync(acc[i][j], af[i], bf[j], acc[i][j]);
        }
        __syncthreads();
    }

    // ---- fused epilogue ----
    float* Cs = sm;
#pragma unroll
    for (int i = 0; i < 4; i++)
#pragma unroll
        for (int j = 0; j < 4; j++)
            wmma::store_matrix_sync(&Cs[(wm * 64 + i * 16) * C_LD + wn * 64 + j * 16],
                                    acc[i][j], C_LD, wmma::mem_row_major);
    __syncthreads();

#pragma unroll
    for (int i = 0; i < 32; i++) {
        int idx = t + i * 256;        // 0..8191 float4 slots
        int r = idx >> 6;             // 0..127
        int c4 = (idx & 63) << 2;     // 0..252
        float* src = &Cs[r * C_LD + c4];
        float4 c = make_float4(src[0], src[1], src[2], src[3]);
        float4 bb = *reinterpret_cast<const float4*>(bias + bn + c4);
        c.x += bb.x; c.y += bb.y; c.z += bb.z; c.w += bb.w;
        if (mode >= 2) {
            c.x = gelu_exact(c.x); c.y = gelu_exact(c.y);
            c.z = gelu_exact(c.z); c.w = gelu_exact(c.w);
        }
        if (mode == 1 || mode == 3) {
            float4 rr = *reinterpret_cast<const float4*>(res + (size_t)(bm + r) * N + bn + c4);
            c.x += rr.x; c.y += rr.y; c.z += rr.z; c.w += rr.w;
        }
        *reinterpret_cast<float4*>(C + (size_t)(bm + r) * N + bn + c4) = c;
    }
}

// ---------------- WMMA flash attention (tf32 tensor cores, causal) ----------------
constexpr int SLD = 72;   // 64 + 8 pad
constexpr int ATT_SMEM = (5 * 64 * SLD + 3 * 64) * 4;

__global__ __launch_bounds__(256) void attn_kernel(const float* __restrict__ qkv,
                                                   float* __restrict__ out)
{
    extern __shared__ float sm[];
    float* Qs = sm;
    float* Ks = Qs + 64 * SLD;
    float* Vs = Ks + 64 * SLD;
    float* Ss = Vs + 64 * SLD;
    float* Os = Ss + 64 * SLD;
    float* mrow = Os + 64 * SLD;
    float* lrow = mrow + 64;
    float* arow = lrow + 64;

    const int qb = blockIdx.x;
    const int bh = blockIdx.y;
    const int b = bh >> 4;
    const int h = bh & 15;
    const int t = threadIdx.x;
    const int warp = t >> 5;
    const int wq = warp >> 1;
    const int wk = warp & 1;

    const float* base = qkv + (size_t)b * kS * kQKV + h * kHD;

#pragma unroll
    for (int i = 0; i < 4; i++) {
        int idx = t + i * 256;
        int r = idx >> 4;
        int c = (idx & 15) << 2;
        float4 v = *reinterpret_cast<const float4*>(base + (size_t)(qb * 64 + r) * kQKV + c);
        float* d = &Qs[r * SLD + c];
        d[0] = v.x * 0.125f; d[1] = v.y * 0.125f;
        d[2] = v.z * 0.125f; d[3] = v.w * 0.125f;
        float* o = &Os[r * SLD + c];
        o[0] = 0.f; o[1] = 0.f; o[2] = 0.f; o[3] = 0.f;
    }
    if (t < 64) { mrow[t] = -1e30f; lrow[t] = 0.f; }

    for (int jb = 0; jb <= qb; jb++) {
        __syncthreads();
#pragma unroll
        for (int i = 0; i < 4; i++) {
            int idx = t + i * 256;
            int r = idx >> 4;
            int c = (idx & 15) << 2;
            const float* kr = base + (size_t)(jb * 64 + r) * kQKV + kD + c;
            float4 kv = *reinterpret_cast<const float4*>(kr);
            float4 vv = *reinterpret_cast<const float4*>(kr + kD);
            float* kd = &Ks[r * SLD + c];
            kd[0] = kv.x; kd[1] = kv.y; kd[2] = kv.z; kd[3] = kv.w;
            float* vd = &Vs[r * SLD + c];
            vd[0] = vv.x; vd[1] = vv.y; vd[2] = vv.z; vd[3] = vv.w;
        }
        __syncthreads();

        {
            wmma::fragment<wmma::accumulator, 16, 16, 8, float> sacc[2];
#pragma unroll
            for (int n = 0; n < 2; n++) wmma::fill_fragment(sacc[n], 0.0f);
#pragma unroll
            for (int kk = 0; kk < 8; kk++) {
                wmma::fragment<wmma::matrix_a, 16, 16, 8, wmma::precision::tf32, wmma::row_major> af;
                wmma::load_matrix_sync(af, &Qs[(wq * 16) * SLD + kk * 8], SLD);
#pragma unroll
                for (int e = 0; e < af.num_elements; e++) af.x[e] = wmma::__float_to_tf32(af.x[e]);
#pragma unroll
                for (int n = 0; n < 2; n++) {
                    wmma::fragment<wmma::matrix_b, 16, 16, 8, wmma::precision::tf32, wmma::col_major> bf;
                    wmma::load_matrix_sync(bf, &Ks[(wk * 32 + n * 16) * SLD + kk * 8], SLD);
#pragma unroll
                    for (int e = 0; e < bf.num_elements; e++) bf.x[e] = wmma::__float_to_tf32(bf.x[e]);
                    wmma::mma_sync(sacc[n], af, bf, sacc[n]);
                }
            }
#pragma unroll
            for (int n = 0; n < 2; n++)
                wmma::store_matrix_sync(&Ss[(wq * 16) * SLD + wk * 32 + n * 16],
                                        sacc[n], SLD, wmma::mem_row_major);
        }
        __syncthreads();

        {
            const int row = t >> 2;
            const int g = t & 3;
            float* srow = &Ss[row * SLD + g * 16];
            const int gq = qb * 64 + row;
            const int cbase = jb * 64 + g * 16;
            float sv[16];
            float mx = -1e30f;
#pragma unroll
            for (int j = 0; j < 16; j++) {
                float xv = srow[j];
                if (jb == qb && cbase + j > gq) xv = -1e30f;
                sv[j] = xv;
                mx = fmaxf(mx, xv);
            }
            mx = fmaxf(mx, __shfl_xor_sync(0xffffffffu, mx, 1));
            mx = fmaxf(mx, __shfl_xor_sync(0xffffffffu, mx, 2));
            float mold = mrow[row];
            float mn = fmaxf(mold, mx);
            float a = __expf(mold - mn);
            float sum = 0.f;
#pragma unroll
            for (int j = 0; j < 16; j++) {
                float p = __expf(sv[j] - mn);
                srow[j] = p;
                sum += p;
            }
            sum += __shfl_xor_sync(0xffffffffu, sum, 1);
            sum += __shfl_xor_sync(0xffffffffu, sum, 2);
            if (g == 0) {
                mrow[row] = mn;
                lrow[row] = lrow[row] * a + sum;
                arow[row] = a;
            }
        }
        __syncthreads();

        wmma::fragment<wmma::accumulator, 16, 16, 8, float> oacc[2];
#pragma unroll
        for (int n = 0; n < 2; n++) wmma::fill_fragment(oacc[n], 0.0f);
#pragma unroll
        for (int kk = 0; kk < 8; kk++) {
            wmma::fragment<wmma::matrix_a, 16, 16, 8, wmma::precision::tf32, wmma::row_major> af;
            wmma::load_matrix_sync(af, &Ss[(wq * 16) * SLD + kk * 8], SLD);
#pragma unroll
            for (int e = 0; e < af.num_elements; e++) af.x[e] = wmma::__float_to_tf32(af.x[e]);
#pragma unroll
            for (int n = 0; n < 2; n++) {
                wmma::fragment<wmma::matrix_b, 16, 16, 8, wmma::precision::tf32, wmma::row_major> bf;
                wmma::load_matrix_sync(bf, &Vs[(kk * 8) * SLD + wk * 32 + n * 16], SLD);
#pragma unroll
                for (int e = 0; e < bf.num_elements; e++) bf.x[e] = wmma::__float_to_tf32(bf.x[e]);
                wmma::mma_sync(oacc[n], af, bf, oacc[n]);
            }
        }
        __syncthreads();
#pragma unroll
        for (int n = 0; n < 2; n++)
            wmma::store_matrix_sync(&Ss[(wq * 16) * SLD + wk * 32 + n * 16],
                                    oacc[n], SLD, wmma::mem_row_major);
        __syncthreads();

#pragma unroll
        for (int i = 0; i < 4; i++) {
            int idx = t + i * 256;
            int r = idx >> 4;
            int c = (idx & 15) << 2;
            float a = arow[r];
            float* od = &Os[r * SLD + c];
            const float* pd = &Ss[r * SLD + c];
            od[0] = od[0] * a + pd[0];
            od[1] = od[1] * a + pd[1];
            od[2] = od[2] * a + pd[2];
            od[3] = od[3] * a + pd[3];
        }
    }
    __syncthreads();

#pragma unroll
    for (int i = 0; i < 4; i++) {
        int idx = t + i * 256;
        int r = idx >> 4;
        int c = (idx & 15) << 2;
        float inv = 1.0f / lrow[r];
        const float* od = &Os[r * SLD + c];
        float4 v = make_float4(od[0] * inv, od[1] * inv, od[2] * inv, od[3] * inv);
        *reinterpret_cast<float4*>(out + (size_t)(b * kS + qb * 64 + r) * kD + h * kHD + c) = v;
    }
}

// ---------------- launch ----------------
extern "C" void kernel_launch(void* const* d_in, const int* in_sizes, int n_in,
                              void* d_out, int out_size)
{
    const float* x    = (const float*)d_in[0];
    const float* Wq   = (const float*)d_in[1];
    const float* bq   = (const float*)d_in[2];
    const float* Wk   = (const float*)d_in[3];
    const float* bk   = (const float*)d_in[4];
    const float* Wv   = (const float*)d_in[5];
    const float* bv   = (const float*)d_in[6];
    const float* Wo   = (const float*)d_in[7];
    const float* bo   = (const float*)d_in[8];
    const float* W1   = (const float*)d_in[9];
    const float* b1   = (const float*)d_in[10];
    const float* W2   = (const float*)d_in[11];
    const float* b2   = (const float*)d_in[12];
    const float* ln1g = (const float*)d_in[13];
    const float* ln1b = (const float*)d_in[14];
    const float* ln2g = (const float*)d_in[15];
    const float* ln2b = (const float*)d_in[16];
    float* out = (float*)d_out;

    float *h1, *wqkv, *bqkv, *qkv, *attn, *x2, *ff1;
    cudaGetSymbolAddress((void**)&h1,   g_h1);
    cudaGetSymbolAddress((void**)&wqkv, g_wqkv);
    cudaGetSymbolAddress((void**)&bqkv, g_bqkv);
    cudaGetSymbolAddress((void**)&qkv,  g_qkv);
    cudaGetSymbolAddress((void**)&attn, g_attn);
    cudaGetSymbolAddress((void**)&x2,   g_x2);
    cudaGetSymbolAddress((void**)&ff1,  g_ff1);

    cudaFuncSetAttribute(attn_kernel, cudaFuncAttributeMaxDynamicSharedMemorySize, ATT_SMEM);
    cudaFuncSetAttribute(gemm_tf32, cudaFuncAttributeMaxDynamicSharedMemorySize, GEMM_SMEM);

    // 1. pack QKV weights/biases
    pack_qkv_kernel<<<(kD * kQKV + 255) / 256, 256>>>(Wq, Wk, Wv, bq, bk, bv);
    // 2. LN1
    ln_kernel<<<kM, 256>>>(x, ln1g, ln1b, h1);
    // 3. QKV projection (+bias fused)
    gemm_tf32<<<dim3(kQKV / GBN, kM / GBM), 256, GEMM_SMEM>>>(h1, wqkv, qkv, bqkv, nullptr,
                                                              kM, kQKV, kD, 0);
    // 4. attention (tf32 wmma flash)
    attn_kernel<<<dim3(kS / 64, kB * kH), 256, ATT_SMEM>>>(qkv, attn);
    // 5. output projection (+bias+residual fused)
    gemm_tf32<<<dim3(kD / GBN, kM / GBM), 256, GEMM_SMEM>>>(attn, Wo, x2, bo, x,
                                                            kM, kD, kD, 1);
    // 6. LN2
    ln_kernel<<<kM, 256>>>(x2, ln2g, ln2b, h1);
    // 7. FFN up (+bias+gelu fused)
    gemm_tf32<<<dim3(kFF / GBN, kM / GBM), 256, GEMM_SMEM>>>(h1, W1, ff1, b1, nullptr,
                                                             kM, kFF, kD, 2);
    // 8. FFN down (+bias+gelu+residual fused) -> out
    gemm_tf32<<<dim3(kD / GBN, kM / GBM), 256, GEMM_SMEM>>>(ff1, W2, out, b2, x2,
                                                            kM, kD, kFF, 3);
}

// round 8
// speedup vs baseline: 1.4185x; 1.0192x over previous
#include <cuda_runtime.h>
#include <mma.h>
#include <cmath>
#include <cstdint>

using namespace nvcuda;

constexpr int kB = 4, kS = 2048, kD = 1024, kH = 16, kHD = 64, kFF = 4096;
constexpr int kM = kB * kS;          // 8192 rows
constexpr int kQKV = 3 * kD;         // 3072

// ---------------- scratch (static device globals; no allocation) ----------------
__device__ float g_h1[(size_t)kM * kD];
__device__ float g_wqkv[(size_t)kD * kQKV];
__device__ float g_bqkv[kQKV];
__device__ float g_qkv[(size_t)kM * kQKV];
__device__ float g_attn[(size_t)kM * kD];
__device__ float g_x2[(size_t)kM * kD];
__device__ float g_ff1[(size_t)kM * kFF];
__device__ float g_wo[(size_t)kD * kD];     // tf32-rounded weights
__device__ float g_w1[(size_t)kD * kFF];
__device__ float g_w2[(size_t)kFF * kD];

// ---------------- helpers ----------------
__device__ __forceinline__ float to_tf32(float x)
{
    float r;
    asm("cvt.rna.tf32.f32 %0, %1;" : "=f"(r) : "f"(x));
    return r;
}

__device__ __forceinline__ void cp_async16(void* smem, const void* gmem)
{
    unsigned int s = (unsigned int)__cvta_generic_to_shared(smem);
    asm volatile("cp.async.cg.shared.global [%0], [%1], 16;\n" :: "r"(s), "l"(gmem));
}

__device__ __forceinline__ float gelu_exact(float x)
{
    return 0.5f * x * (1.0f + erff(x * 0.70710678118654752f));
}

// ---------------- weight rounding (tf32 pre-round) ----------------
__global__ void round_kernel(const float* __restrict__ src, float* __restrict__ dst, int n4)
{
    int i = blockIdx.x * blockDim.x + threadIdx.x;
    if (i >= n4) return;
    float4 v = reinterpret_cast<const float4*>(src)[i];
    v.x = to_tf32(v.x); v.y = to_tf32(v.y); v.z = to_tf32(v.z); v.w = to_tf32(v.w);
    reinterpret_cast<float4*>(dst)[i] = v;
}

// ---------------- weight/bias packing (rounds to tf32) ----------------
__global__ void pack_qkv_kernel(const float* __restrict__ Wq, const float* __restrict__ Wk,
                                const float* __restrict__ Wv, const float* __restrict__ bq,
                                const float* __restrict__ bk, const float* __restrict__ bv)
{
    int idx = blockIdx.x * blockDim.x + threadIdx.x;
    const int total = kD * kQKV;
    if (idx >= total) return;
    int d = idx / kQKV;
    int n = idx % kQKV;
    int sect = n / kD;
    int c = n % kD;
    int h = c / kHD;
    int e = c % kHD;
    const float* W = (sect == 0) ? Wq : (sect == 1) ? Wk : Wv;
    g_wqkv[idx] = to_tf32(W[((size_t)h * kD + d) * kHD + e]);
    if (idx < kQKV) {
        const float* bb = (idx < kD) ? bq : (idx < 2 * kD) ? bk : bv;
        g_bqkv[idx] = bb[idx % kD];
    }
}

// ---------------- LayerNorm (one block per row, D=1024; output tf32-rounded) ----------------
__global__ void ln_kernel(const float* __restrict__ x, const float* __restrict__ g,
                          const float* __restrict__ beta, float* __restrict__ o)
{
    __shared__ float red[8];
    int row = blockIdx.x;
    int t = threadIdx.x;  // 256
    float4 v = reinterpret_cast<const float4*>(x + (size_t)row * kD)[t];
    float s = v.x + v.y + v.z + v.w;
#pragma unroll
    for (int off = 16; off; off >>= 1) s += __shfl_xor_sync(0xffffffffu, s, off);
    if ((t & 31) == 0) red[t >> 5] = s;
    __syncthreads();
    float tot = 0.f;
#pragma unroll
    for (int i = 0; i < 8; i++) tot += red[i];
    float mu = tot * (1.0f / kD);
    __syncthreads();
    float d0 = v.x - mu, d1 = v.y - mu, d2 = v.z - mu, d3 = v.w - mu;
    float s2 = d0 * d0 + d1 * d1 + d2 * d2 + d3 * d3;
#pragma unroll
    for (int off = 16; off; off >>= 1) s2 += __shfl_xor_sync(0xffffffffu, s2, off);
    if ((t & 31) == 0) red[t >> 5] = s2;
    __syncthreads();
    float tot2 = 0.f;
#pragma unroll
    for (int i = 0; i < 8; i++) tot2 += red[i];
    float inv = rsqrtf(tot2 * (1.0f / kD) + 1e-5f);
    float4 gg = reinterpret_cast<const float4*>(g)[t];
    float4 bb = reinterpret_cast<const float4*>(beta)[t];
    float4 r;
    r.x = to_tf32(d0 * inv * gg.x + bb.x);
    r.y = to_tf32(d1 * inv * gg.y + bb.y);
    r.z = to_tf32(d2 * inv * gg.z + bb.z);
    r.w = to_tf32(d3 * inv * gg.w + bb.w);
    reinterpret_cast<float4*>(o + (size_t)row * kD)[t] = r;
}

// ---------------- TF32 WMMA GEMM: 128x256 block, 64x64 warp, 3-stage cp.async ----------------
// Inputs MUST already be tf32-rounded. Epilogue:
// mode 0: C + bias            mode 1: C + bias + res
// mode 2: gelu(C + bias)      mode 3: gelu(C + bias) + res
// rnd != 0: round output to tf32 (for tensors consumed only as GEMM/MMA inputs)
constexpr int GBM = 128, GBN = 256, GBK = 32;
constexpr int NSTAGE = 3;
constexpr int A_LD = 40;
constexpr int B_LD = 264;
constexpr int C_LD = 264;
constexpr int ASZ = GBM * A_LD;
constexpr int BSZ = GBK * B_LD;
constexpr int STAGE = ASZ + BSZ;
constexpr int GEMM_SMEM = NSTAGE * STAGE * 4;

__global__ __launch_bounds__(256, 1) void gemm_tf32(const float* __restrict__ A,
                                                    const float* __restrict__ Bm,
                                                    float* __restrict__ C,
                                                    const float* __restrict__ bias,
                                                    const float* __restrict__ res,
                                                    int M, int N, int K, int mode, int rnd)
{
    extern __shared__ float sm[];

    const int bm = blockIdx.y * GBM;
    const int bn = blockIdx.x * GBN;
    const int t = threadIdx.x;
    const int warp = t >> 5;
    const int wm = warp >> 2;
    const int wn = warp & 3;

    wmma::fragment<wmma::accumulator, 16, 16, 8, float> acc[4][4];
#pragma unroll
    for (int i = 0; i < 4; i++)
#pragma unroll
        for (int j = 0; j < 4; j++) wmma::fill_fragment(acc[i][j], 0.0f);

    const int ar = t >> 3;
    const int ac = (t & 7) << 2;
    const int br = t >> 6;
    const int bc = (t & 63) << 2;

    const int KT = K / GBK;

    auto load_tile = [&](int kt, int buf) {
        float* As = sm + buf * STAGE;
        float* Bs = As + ASZ;
        const float* Ab = A + (size_t)bm * K + (size_t)kt * GBK;
        const float* Bb = Bm + (size_t)kt * GBK * N + bn;
#pragma unroll
        for (int i = 0; i < 4; i++) {
            int r = ar + i * 32;
            cp_async16(&As[r * A_LD + ac], Ab + (size_t)r * K + ac);
        }
#pragma unroll
        for (int i = 0; i < 8; i++) {
            int r = br + i * 4;
            cp_async16(&Bs[r * B_LD + bc], Bb + (size_t)r * N + bc);
        }
        asm volatile("cp.async.commit_group;\n");
    };

    load_tile(0, 0);
    load_tile(1, 1);

    for (int kt = 0; kt < KT; kt++) {
        const int buf = kt % NSTAGE;
        if (kt + 2 < KT) {
            load_tile(kt + 2, (kt + 2) % NSTAGE);
            asm volatile("cp.async.wait_group 2;\n");
        } else if (kt + 1 < KT) {
            asm volatile("cp.async.wait_group 1;\n");
        } else {
            asm volatile("cp.async.wait_group 0;\n");
        }
        __syncthreads();

        const float* As = sm + buf * STAGE;
        const float* Bs = As + ASZ;
#pragma unroll
        for (int kk = 0; kk < 4; kk++) {
            wmma::fragment<wmma::matrix_a, 16, 16, 8, wmma::precision::tf32, wmma::row_major> af[4];
            wmma::fragment<wmma::matrix_b, 16, 16, 8, wmma::precision::tf32, wmma::row_major> bf[4];
#pragma unroll
            for (int i = 0; i < 4; i++)
                wmma::load_matrix_sync(af[i], &As[(wm * 64 + i * 16) * A_LD + kk * 8], A_LD);
#pragma unroll
            for (int j = 0; j < 4; j++)
                wmma::load_matrix_sync(bf[j], &Bs[(kk * 8) * B_LD + wn * 64 + j * 16], B_LD);
#pragma unroll
            for (int i = 0; i < 4; i++)
#pragma unroll
                for (int j = 0; j < 4; j++)
                    wmma::mma_sync(acc[i][j], af[i], bf[j], acc[i][j]);
        }
        __syncthreads();
    }

    // ---- fused epilogue ----
    float* Cs = sm;
#pragma unroll
    for (int i = 0; i < 4; i++)
#pragma unroll
        for (int j = 0; j < 4; j++)
            wmma::store_matrix_sync(&Cs[(wm * 64 + i * 16) * C_LD + wn * 64 + j * 16],
                                    acc[i][j], C_LD, wmma::mem_row_major);
    __syncthreads();

#pragma unroll
    for (int i = 0; i < 32; i++) {
        int idx = t + i * 256;
        int r = idx >> 6;
        int c4 = (idx & 63) << 2;
        float* src = &Cs[r * C_LD + c4];
        float4 c = make_float4(src[0], src[1], src[2], src[3]);
        float4 bb = *reinterpret_cast<const float4*>(bias + bn + c4);
        c.x += bb.x; c.y += bb.y; c.z += bb.z; c.w += bb.w;
        if (mode >= 2) {
            c.x = gelu_exact(c.x); c.y = gelu_exact(c.y);
            c.z = gelu_exact(c.z); c.w = gelu_exact(c.w);
        }
        if (mode == 1 || mode == 3) {
            float4 rr = *reinterpret_cast<const float4*>(res + (size_t)(bm + r) * N + bn + c4);
            c.x += rr.x; c.y += rr.y; c.z += rr.z; c.w += rr.w;
        }
        if (rnd) {
            c.x = to_tf32(c.x); c.y = to_tf32(c.y);
            c.z = to_tf32(c.z); c.w = to_tf32(c.w);
        }
        *reinterpret_cast<float4*>(C + (size_t)(bm + r) * N + bn + c4) = c;
    }
}

// ---------------- WMMA flash attention (tf32 tensor cores, causal) ----------------
// qkv entries are tf32-rounded already; P rounded scalar at softmax store.
constexpr int SLD = 72;
constexpr int ATT_SMEM = (5 * 64 * SLD + 3 * 64) * 4;

__global__ __launch_bounds__(256) void attn_kernel(const float* __restrict__ qkv,
                                                   float* __restrict__ out)
{
    extern __shared__ float sm[];
    float* Qs = sm;
    float* Ks = Qs + 64 * SLD;
    float* Vs = Ks + 64 * SLD;
    float* Ss = Vs + 64 * SLD;
    float* Os = Ss + 64 * SLD;
    float* mrow = Os + 64 * SLD;
    float* lrow = mrow + 64;
    float* arow = lrow + 64;

    const int qb = blockIdx.x;
    const int bh = blockIdx.y;
    const int b = bh >> 4;
    const int h = bh & 15;
    const int t = threadIdx.x;
    const int warp = t >> 5;
    const int wq = warp >> 1;
    const int wk = warp & 1;

    const float* base = qkv + (size_t)b * kS * kQKV + h * kHD;

#pragma unroll
    for (int i = 0; i < 4; i++) {
        int idx = t + i * 256;
        int r = idx >> 4;
        int c = (idx & 15) << 2;
        float4 v = *reinterpret_cast<const float4*>(base + (size_t)(qb * 64 + r) * kQKV + c);
        float* d = &Qs[r * SLD + c];
        d[0] = v.x * 0.125f; d[1] = v.y * 0.125f;   // exact scale, stays tf32
        d[2] = v.z * 0.125f; d[3] = v.w * 0.125f;
        float* o = &Os[r * SLD + c];
        o[0] = 0.f; o[1] = 0.f; o[2] = 0.f; o[3] = 0.f;
    }
    if (t < 64) { mrow[t] = -1e30f; lrow[t] = 0.f; }

    for (int jb = 0; jb <= qb; jb++) {
        __syncthreads();
#pragma unroll
        for (int i = 0; i < 4; i++) {
            int idx = t + i * 256;
            int r = idx >> 4;
            int c = (idx & 15) << 2;
            const float* kr = base + (size_t)(jb * 64 + r) * kQKV + kD + c;
            float4 kv = *reinterpret_cast<const float4*>(kr);
            float4 vv = *reinterpret_cast<const float4*>(kr + kD);
            float* kd = &Ks[r * SLD + c];
            kd[0] = kv.x; kd[1] = kv.y; kd[2] = kv.z; kd[3] = kv.w;
            float* vd = &Vs[r * SLD + c];
            vd[0] = vv.x; vd[1] = vv.y; vd[2] = vv.z; vd[3] = vv.w;
        }
        __syncthreads();

        {
            wmma::fragment<wmma::accumulator, 16, 16, 8, float> sacc[2];
#pragma unroll
            for (int n = 0; n < 2; n++) wmma::fill_fragment(sacc[n], 0.0f);
#pragma unroll
            for (int kk = 0; kk < 8; kk++) {
                wmma::fragment<wmma::matrix_a, 16, 16, 8, wmma::precision::tf32, wmma::row_major> af;
                wmma::load_matrix_sync(af, &Qs[(wq * 16) * SLD + kk * 8], SLD);
#pragma unroll
                for (int n = 0; n < 2; n++) {
                    wmma::fragment<wmma::matrix_b, 16, 16, 8, wmma::precision::tf32, wmma::col_major> bf;
                    wmma::load_matrix_sync(bf, &Ks[(wk * 32 + n * 16) * SLD + kk * 8], SLD);
                    wmma::mma_sync(sacc[n], af, bf, sacc[n]);
                }
            }
#pragma unroll
            for (int n = 0; n < 2; n++)
                wmma::store_matrix_sync(&Ss[(wq * 16) * SLD + wk * 32 + n * 16],
                                        sacc[n], SLD, wmma::mem_row_major);
        }
        __syncthreads();

        {
            const int row = t >> 2;
            const int g = t & 3;
            float* srow = &Ss[row * SLD + g * 16];
            const int gq = qb * 64 + row;
            const int cbase = jb * 64 + g * 16;
            float sv[16];
            float mx = -1e30f;
#pragma unroll
            for (int j = 0; j < 16; j++) {
                float xv = srow[j];
                if (jb == qb && cbase + j > gq) xv = -1e30f;
                sv[j] = xv;
                mx = fmaxf(mx, xv);
            }
            mx = fmaxf(mx, __shfl_xor_sync(0xffffffffu, mx, 1));
            mx = fmaxf(mx, __shfl_xor_sync(0xffffffffu, mx, 2));
            float mold = mrow[row];
            float mn = fmaxf(mold, mx);
            float a = __expf(mold - mn);
            float sum = 0.f;
#pragma unroll
            for (int j = 0; j < 16; j++) {
                float p = __expf(sv[j] - mn);
                srow[j] = to_tf32(p);       // pre-round P for MMA
                sum += p;
            }
            sum += __shfl_xor_sync(0xffffffffu, sum, 1);
            sum += __shfl_xor_sync(0xffffffffu, sum, 2);
            if (g == 0) {
                mrow[row] = mn;
                lrow[row] = lrow[row] * a + sum;
                arow[row] = a;
            }
        }
        __syncthreads();

        wmma::fragment<wmma::accumulator, 16, 16, 8, float> oacc[2];
#pragma unroll
        for (int n = 0; n < 2; n++) wmma::fill_fragment(oacc[n], 0.0f);
#pragma unroll
        for (int kk = 0; kk < 8; kk++) {
            wmma::fragment<wmma::matrix_a, 16, 16, 8, wmma::precision::tf32, wmma::row_major> af;
            wmma::load_matrix_sync(af, &Ss[(wq * 16) * SLD + kk * 8], SLD);
#pragma unroll
            for (int n = 0; n < 2; n++) {
                wmma::fragment<wmma::matrix_b, 16, 16, 8, wmma::precision::tf32, wmma::row_major> bf;
                wmma::load_matrix_sync(bf, &Vs[(kk * 8) * SLD + wk * 32 + n * 16], SLD);
                wmma::mma_sync(oacc[n], af, bf, oacc[n]);
            }
        }
        __syncthreads();
#pragma unroll
        for (int n = 0; n < 2; n++)
            wmma::store_matrix_sync(&Ss[(wq * 16) * SLD + wk * 32 + n * 16],
                                    oacc[n], SLD, wmma::mem_row_major);
        __syncthreads();

#pragma unroll
        for (int i = 0; i < 4; i++) {
            int idx = t + i * 256;
            int r = idx >> 4;
            int c = (idx & 15) << 2;
            float a = arow[r];
            float* od = &Os[r * SLD + c];
            const float* pd = &Ss[r * SLD + c];
            od[0] = od[0] * a + pd[0];
            od[1] = od[1] * a + pd[1];
            od[2] = od[2] * a + pd[2];
            od[3] = od[3] * a + pd[3];
        }
    }
    __syncthreads();

#pragma unroll
    for (int i = 0; i < 4; i++) {
        int idx = t + i * 256;
        int r = idx >> 4;
        int c = (idx & 15) << 2;
        float inv = 1.0f / lrow[r];
        const float* od = &Os[r * SLD + c];
        float4 v = make_float4(to_tf32(od[0] * inv), to_tf32(od[1] * inv),
                               to_tf32(od[2] * inv), to_tf32(od[3] * inv));
        *reinterpret_cast<float4*>(out + (size_t)(b * kS + qb * 64 + r) * kD + h * kHD + c) = v;
    }
}

// ---------------- launch ----------------
extern "C" void kernel_launch(void* const* d_in, const int* in_sizes, int n_in,
                              void* d_out, int out_size)
{
    const float* x    = (const float*)d_in[0];
    const float* Wq   = (const float*)d_in[1];
    const float* bq   = (const float*)d_in[2];
    const float* Wk   = (const float*)d_in[3];
    const float* bk   = (const float*)d_in[4];
    const float* Wv   = (const float*)d_in[5];
    const float* bv   = (const float*)d_in[6];
    const float* Wo   = (const float*)d_in[7];
    const float* bo   = (const float*)d_in[8];
    const float* W1   = (const float*)d_in[9];
    const float* b1   = (const float*)d_in[10];
    const float* W2   = (const float*)d_in[11];
    const float* b2   = (const float*)d_in[12];
    const float* ln1g = (const float*)d_in[13];
    const float* ln1b = (const float*)d_in[14];
    const float* ln2g = (const float*)d_in[15];
    const float* ln2b = (const float*)d_in[16];
    float* out = (float*)d_out;

    float *h1, *wqkv, *bqkv, *qkv, *attn, *x2, *ff1, *wo, *w1, *w2;
    cudaGetSymbolAddress((void**)&h1,   g_h1);
    cudaGetSymbolAddress((void**)&wqkv, g_wqkv);
    cudaGetSymbolAddress((void**)&bqkv, g_bqkv);
    cudaGetSymbolAddress((void**)&qkv,  g_qkv);
    cudaGetSymbolAddress((void**)&attn, g_attn);
    cudaGetSymbolAddress((void**)&x2,   g_x2);
    cudaGetSymbolAddress((void**)&ff1,  g_ff1);
    cudaGetSymbolAddress((void**)&wo,   g_wo);
    cudaGetSymbolAddress((void**)&w1,   g_w1);
    cudaGetSymbolAddress((void**)&w2,   g_w2);

    cudaFuncSetAttribute(attn_kernel, cudaFuncAttributeMaxDynamicSharedMemorySize, ATT_SMEM);
    cudaFuncSetAttribute(gemm_tf32, cudaFuncAttributeMaxDynamicSharedMemorySize, GEMM_SMEM);

    // 0. round weights to tf32 once
    round_kernel<<<(kD * kD / 4 + 255) / 256, 256>>>(Wo, wo, kD * kD / 4);
    round_kernel<<<(kD * kFF / 4 + 255) / 256, 256>>>(W1, w1, kD * kFF / 4);
    round_kernel<<<(kFF * kD / 4 + 255) / 256, 256>>>(W2, w2, kFF * kD / 4);
    // 1. pack QKV weights/biases (rounds)
    pack_qkv_kernel<<<(kD * kQKV + 255) / 256, 256>>>(Wq, Wk, Wv, bq, bk, bv);
    // 2. LN1 (output rounded)
    ln_kernel<<<kM, 256>>>(x, ln1g, ln1b, h1);
    // 3. QKV projection (+bias, output rounded)
    gemm_tf32<<<dim3(kQKV / GBN, kM / GBM), 256, GEMM_SMEM>>>(h1, wqkv, qkv, bqkv, nullptr,
                                                              kM, kQKV, kD, 0, 1);
    // 4. attention (output rounded)
    attn_kernel<<<dim3(kS / 64, kB * kH), 256, ATT_SMEM>>>(qkv, attn);
    // 5. output projection (+bias+residual, NOT rounded)
    gemm_tf32<<<dim3(kD / GBN, kM / GBM), 256, GEMM_SMEM>>>(attn, wo, x2, bo, x,
                                                            kM, kD, kD, 1, 0);
    // 6. LN2 (output rounded)
    ln_kernel<<<kM, 256>>>(x2, ln2g, ln2b, h1);
    // 7. FFN up (+bias+gelu, output rounded)
    gemm_tf32<<<dim3(kFF / GBN, kM / GBM), 256, GEMM_SMEM>>>(h1, w1, ff1, b1, nullptr,
                                                             kM, kFF, kD, 2, 1);
    // 8. FFN down (+bias+gelu+residual, NOT rounded) -> out
    gemm_tf32<<<dim3(kD / GBN, kM / GBM), 256, GEMM_SMEM>>>(ff1, w2, out, b2, x2,
                                                            kM, kD, kFF, 3, 0);
}

// round 9
// speedup vs baseline: 4.0956x; 2.8872x over previous
#include <cuda_runtime.h>
#include <cuda_fp16.h>
#include <mma.h>
#include <cmath>
#include <cstdint>

using namespace nvcuda;

constexpr int kB = 4, kS = 2048, kD = 1024, kH = 16, kHD = 64, kFF = 4096;
constexpr int kM = kB * kS;          // 8192 rows
constexpr int kQKV = 3 * kD;         // 3072

// ---------------- scratch (static device globals; no allocation) ----------------
__device__ __half g_h1[(size_t)kM * kD];        // LN out (fp16)
__device__ __half g_wqkv[(size_t)kD * kQKV];    // packed QKV weight (fp16)
__device__ float  g_bqkv[kQKV];
__device__ float  g_qkv[(size_t)kM * kQKV];     // q|k|v fp32 (attention converts)
__device__ __half g_attn[(size_t)kM * kD];      // attention out (fp16)
__device__ float  g_x2[(size_t)kM * kD];        // residual after attention (fp32)
__device__ __half g_ff1[(size_t)kM * kFF];      // FFN hidden (fp16)
__device__ __half g_wo[(size_t)kD * kD];
__device__ __half g_w1[(size_t)kD * kFF];
__device__ __half g_w2[(size_t)kFF * kD];

// ---------------- helpers ----------------
__device__ __forceinline__ void cp_async16(void* smem, const void* gmem)
{
    unsigned int s = (unsigned int)__cvta_generic_to_shared(smem);
    asm volatile("cp.async.cg.shared.global [%0], [%1], 16;\n" :: "r"(s), "l"(gmem));
}

__device__ __forceinline__ float gelu_exact(float x)
{
    return 0.5f * x * (1.0f + erff(x * 0.70710678118654752f));
}

__device__ __forceinline__ void store_half4(__half* dst, float a, float b, float c, float d)
{
    __half2 h0 = __floats2half2_rn(a, b);
    __half2 h1 = __floats2half2_rn(c, d);
    uint2 u;
    u.x = *reinterpret_cast<unsigned int*>(&h0);
    u.y = *reinterpret_cast<unsigned int*>(&h1);
    *reinterpret_cast<uint2*>(dst) = u;
}

// ---------------- fp32 -> fp16 weight conversion ----------------
__global__ void tohalf_kernel(const float* __restrict__ src, __half* __restrict__ dst, int n4)
{
    int i = blockIdx.x * blockDim.x + threadIdx.x;
    if (i >= n4) return;
    float4 v = reinterpret_cast<const float4*>(src)[i];
    store_half4(dst + (size_t)i * 4, v.x, v.y, v.z, v.w);
}

// ---------------- weight/bias packing (fp16) ----------------
__global__ void pack_qkv_kernel(const float* __restrict__ Wq, const float* __restrict__ Wk,
                                const float* __restrict__ Wv, const float* __restrict__ bq,
                                const float* __restrict__ bk, const float* __restrict__ bv)
{
    int idx = blockIdx.x * blockDim.x + threadIdx.x;
    const int total = kD * kQKV;
    if (idx >= total) return;
    int d = idx / kQKV;
    int n = idx % kQKV;
    int sect = n / kD;
    int c = n % kD;
    int h = c / kHD;
    int e = c % kHD;
    const float* W = (sect == 0) ? Wq : (sect == 1) ? Wk : Wv;
    g_wqkv[idx] = __float2half(W[((size_t)h * kD + d) * kHD + e]);
    if (idx < kQKV) {
        const float* bb = (idx < kD) ? bq : (idx < 2 * kD) ? bk : bv;
        g_bqkv[idx] = bb[idx % kD];
    }
}

// ---------------- LayerNorm (one block per row; fp16 output) ----------------
__global__ void ln_kernel(const float* __restrict__ x, const float* __restrict__ g,
                          const float* __restrict__ beta, __half* __restrict__ o)
{
    __shared__ float red[8];
    int row = blockIdx.x;
    int t = threadIdx.x;  // 256
    float4 v = reinterpret_cast<const float4*>(x + (size_t)row * kD)[t];
    float s = v.x + v.y + v.z + v.w;
#pragma unroll
    for (int off = 16; off; off >>= 1) s += __shfl_xor_sync(0xffffffffu, s, off);
    if ((t & 31) == 0) red[t >> 5] = s;
    __syncthreads();
    float tot = 0.f;
#pragma unroll
    for (int i = 0; i < 8; i++) tot += red[i];
    float mu = tot * (1.0f / kD);
    __syncthreads();
    float d0 = v.x - mu, d1 = v.y - mu, d2 = v.z - mu, d3 = v.w - mu;
    float s2 = d0 * d0 + d1 * d1 + d2 * d2 + d3 * d3;
#pragma unroll
    for (int off = 16; off; off >>= 1) s2 += __shfl_xor_sync(0xffffffffu, s2, off);
    if ((t & 31) == 0) red[t >> 5] = s2;
    __syncthreads();
    float tot2 = 0.f;
#pragma unroll
    for (int i = 0; i < 8; i++) tot2 += red[i];
    float inv = rsqrtf(tot2 * (1.0f / kD) + 1e-5f);
    float4 gg = reinterpret_cast<const float4*>(g)[t];
    float4 bb = reinterpret_cast<const float4*>(beta)[t];
    store_half4(o + (size_t)row * kD + t * 4,
                d0 * inv * gg.x + bb.x, d1 * inv * gg.y + bb.y,
                d2 * inv * gg.z + bb.z, d3 * inv * gg.w + bb.w);
}

// ---------------- FP16 WMMA GEMM: 128x256 block, 64x64 warp, 4-stage cp.async ----------------
// mode 0: +bias   1: +bias+res   2: gelu(+bias)   3: gelu(+bias)+res
// out16 != 0 -> write C16 (fp16, staged), else C32 (fp32, direct fragment store)
constexpr int GBM = 128, GBN = 256, GBK = 32;
constexpr int NSTAGE = 4;
constexpr int A_LDh = 40;           // halfs (32 + 8)
constexpr int B_LDh = 264;          // halfs (256 + 8)
constexpr int ASZh = GBM * A_LDh;   // 5120 halfs
constexpr int BSZh = GBK * B_LDh;   // 8448 halfs
constexpr int STAGEh = ASZh + BSZh; // 13568 halfs = 27136 B
constexpr int GEMM_SMEM = NSTAGE * STAGEh * 2;   // 108544 B
constexpr int C_LDf = 264;

__global__ __launch_bounds__(256, 1) void gemm_h(const __half* __restrict__ A,
                                                 const __half* __restrict__ Bm,
                                                 float* __restrict__ C32,
                                                 __half* __restrict__ C16,
                                                 const float* __restrict__ bias,
                                                 const float* __restrict__ res,
                                                 int M, int N, int K, int mode, int out16)
{
    extern __shared__ char smc[];

    const int bm = blockIdx.y * GBM;
    const int bn = blockIdx.x * GBN;
    const int t = threadIdx.x;
    const int warp = t >> 5;
    const int wm = warp >> 2;   // 0..1 -> 64 rows
    const int wn = warp & 3;    // 0..3 -> 64 cols

    wmma::fragment<wmma::accumulator, 16, 16, 16, float> acc[4][4];
#pragma unroll
    for (int i = 0; i < 4; i++)
#pragma unroll
        for (int j = 0; j < 4; j++) wmma::fill_fragment(acc[i][j], 0.0f);

    const int KT = K / GBK;

    auto load_tile = [&](int kt, int buf) {
        __half* As = reinterpret_cast<__half*>(smc) + buf * STAGEh;
        __half* Bs = As + ASZh;
        const __half* Ab = A + (size_t)bm * K + (size_t)kt * GBK;
        const __half* Bb = Bm + (size_t)kt * GBK * N + bn;
#pragma unroll
        for (int i = 0; i < 2; i++) {
            int ch = t + i * 256;          // 0..511  (A: 128 rows x 4 chunks)
            int r = ch >> 2;
            int c = (ch & 3) * 8;
            cp_async16(&As[r * A_LDh + c], Ab + (size_t)r * K + c);
        }
#pragma unroll
        for (int i = 0; i < 4; i++) {
            int ch = t + i * 256;          // 0..1023 (B: 32 rows x 32 chunks)
            int r = ch >> 5;
            int c = (ch & 31) * 8;
            cp_async16(&Bs[r * B_LDh + c], Bb + (size_t)r * N + c);
        }
        asm volatile("cp.async.commit_group;\n");
    };

    load_tile(0, 0);
    load_tile(1, 1);
    load_tile(2, 2);

    for (int kt = 0; kt < KT; kt++) {
        const int buf = kt % NSTAGE;
        if (kt + 3 < KT) {
            load_tile(kt + 3, (kt + 3) % NSTAGE);
            asm volatile("cp.async.wait_group 3;\n");
        } else if (kt + 2 < KT) {
            asm volatile("cp.async.wait_group 2;\n");
        } else if (kt + 1 < KT) {
            asm volatile("cp.async.wait_group 1;\n");
        } else {
            asm volatile("cp.async.wait_group 0;\n");
        }
        __syncthreads();

        const __half* As = reinterpret_cast<const __half*>(smc) + buf * STAGEh;
        const __half* Bs = As + ASZh;
#pragma unroll
        for (int kk = 0; kk < 2; kk++) {
            wmma::fragment<wmma::matrix_a, 16, 16, 16, __half, wmma::row_major> af[4];
            wmma::fragment<wmma::matrix_b, 16, 16, 16, __half, wmma::row_major> bf[4];
#pragma unroll
            for (int i = 0; i < 4; i++)
                wmma::load_matrix_sync(af[i], &As[(wm * 64 + i * 16) * A_LDh + kk * 16], A_LDh);
#pragma unroll
            for (int j = 0; j < 4; j++)
                wmma::load_matrix_sync(bf[j], &Bs[(kk * 16) * B_LDh + wn * 64 + j * 16], B_LDh);
#pragma unroll
            for (int i = 0; i < 4; i++)
#pragma unroll
                for (int j = 0; j < 4; j++)
                    wmma::mma_sync(acc[i][j], af[i], bf[j], acc[i][j]);
        }
        __syncthreads();
    }

    // ---- epilogue in fragments ----
    float* smf = reinterpret_cast<float*>(smc);

    // bias broadcast tile: 16 replicated rows of the 256-wide bias slice
#pragma unroll
    for (int i = 0; i < 16; i++) {
        int idx = t + i * 256;         // 0..4095
        int r = idx >> 8;              // 0..15
        int c = idx & 255;
        smf[r * C_LDf + c] = bias[bn + c];
    }
    __syncthreads();

    wmma::fragment<wmma::accumulator, 16, 16, 16, float> bfr[4];
#pragma unroll
    for (int j = 0; j < 4; j++)
        wmma::load_matrix_sync(bfr[j], &smf[wn * 64 + j * 16], C_LDf, wmma::mem_row_major);
    __syncthreads();   // done reading bias tile before smem reuse

#pragma unroll
    for (int i = 0; i < 4; i++)
#pragma unroll
        for (int j = 0; j < 4; j++) {
#pragma unroll
            for (int e = 0; e < acc[i][j].num_elements; e++) {
                float v = acc[i][j].x[e] + bfr[j].x[e];
                if (mode >= 2) v = gelu_exact(v);
                acc[i][j].x[e] = v;
            }
            if (mode == 1 || mode == 3) {
                wmma::fragment<wmma::accumulator, 16, 16, 16, float> rf;
                wmma::load_matrix_sync(rf, res + (size_t)(bm + wm * 64 + i * 16) * N + bn + wn * 64 + j * 16,
                                       N, wmma::mem_row_major);
#pragma unroll
                for (int e = 0; e < acc[i][j].num_elements; e++)
                    acc[i][j].x[e] += rf.x[e];
            }
        }

    if (!out16) {
#pragma unroll
        for (int i = 0; i < 4; i++)
#pragma unroll
            for (int j = 0; j < 4; j++)
                wmma::store_matrix_sync(C32 + (size_t)(bm + wm * 64 + i * 16) * N + bn + wn * 64 + j * 16,
                                        acc[i][j], N, wmma::mem_row_major);
    } else {
        // two-pass smem staging for fp16 conversion (64 block-rows per pass)
#pragma unroll
        for (int pass = 0; pass < 2; pass++) {
#pragma unroll
            for (int ii = 0; ii < 2; ii++) {
                int i = pass * 2 + ii;
                int sr = wm * 32 + ii * 16;     // smem row base
#pragma unroll
                for (int j = 0; j < 4; j++)
                    wmma::store_matrix_sync(&smf[sr * C_LDf + wn * 64 + j * 16],
                                            acc[i][j], C_LDf, wmma::mem_row_major);
            }
            __syncthreads();
#pragma unroll
            for (int it = 0; it < 16; it++) {
                int idx = t + it * 256;        // 0..4095 float4 slots
                int sr = idx >> 6;             // 0..63
                int c4 = (idx & 63) << 2;
                int gr = (sr & 31) + (sr >> 5) * 64 + pass * 32;
                const float* src = &smf[sr * C_LDf + c4];
                store_half4(C16 + (size_t)(bm + gr) * N + bn + c4,
                            src[0], src[1], src[2], src[3]);
            }
            __syncthreads();
        }
    }
}

// ---------------- FP16 WMMA flash attention (causal) ----------------
constexpr int QLD = 72;   // half stride
constexpr int ATT_SMEM = 4 * 64 * QLD * 2 + (2 * 64 * QLD + 3 * 64) * 4;  // 74496 B

__global__ __launch_bounds__(256) void attn_kernel(const float* __restrict__ qkv,
                                                   __half* __restrict__ out)
{
    extern __shared__ char smc[];
    __half* Qs = reinterpret_cast<__half*>(smc);
    __half* Ks = Qs + 64 * QLD;
    __half* Vs = Ks + 64 * QLD;
    __half* Ps = Vs + 64 * QLD;
    float*  Ss = reinterpret_cast<float*>(Ps + 64 * QLD);
    float*  Os = Ss + 64 * QLD;
    float*  mrow = Os + 64 * QLD;
    float*  lrow = mrow + 64;
    float*  arow = lrow + 64;

    const int qb = blockIdx.x;
    const int bh = blockIdx.y;
    const int b = bh >> 4;
    const int h = bh & 15;
    const int t = threadIdx.x;
    const int warp = t >> 5;
    const int wq = warp >> 1;
    const int wk = warp & 1;

    const float* base = qkv + (size_t)b * kS * kQKV + h * kHD;

#pragma unroll
    for (int i = 0; i < 4; i++) {
        int idx = t + i * 256;
        int r = idx >> 4;
        int c = (idx & 15) << 2;
        float4 v = *reinterpret_cast<const float4*>(base + (size_t)(qb * 64 + r) * kQKV + c);
        store_half4(&Qs[r * QLD + c], v.x * 0.125f, v.y * 0.125f, v.z * 0.125f, v.w * 0.125f);
        float* o = &Os[r * QLD + c];
        o[0] = 0.f; o[1] = 0.f; o[2] = 0.f; o[3] = 0.f;
    }
    if (t < 64) { mrow[t] = -1e30f; lrow[t] = 0.f; }

    for (int jb = 0; jb <= qb; jb++) {
        __syncthreads();
#pragma unroll
        for (int i = 0; i < 4; i++) {
            int idx = t + i * 256;
            int r = idx >> 4;
            int c = (idx & 15) << 2;
            const float* kr = base + (size_t)(jb * 64 + r) * kQKV + kD + c;
            float4 kv = *reinterpret_cast<const float4*>(kr);
            float4 vv = *reinterpret_cast<const float4*>(kr + kD);
            store_half4(&Ks[r * QLD + c], kv.x, kv.y, kv.z, kv.w);
            store_half4(&Vs[r * QLD + c], vv.x, vv.y, vv.z, vv.w);
        }
        __syncthreads();

        // ---- S = Q @ K^T ----
        {
            wmma::fragment<wmma::accumulator, 16, 16, 16, float> sacc[2];
#pragma unroll
            for (int n = 0; n < 2; n++) wmma::fill_fragment(sacc[n], 0.0f);
#pragma unroll
            for (int kk = 0; kk < 4; kk++) {
                wmma::fragment<wmma::matrix_a, 16, 16, 16, __half, wmma::row_major> af;
                wmma::load_matrix_sync(af, &Qs[(wq * 16) * QLD + kk * 16], QLD);
#pragma unroll
                for (int n = 0; n < 2; n++) {
                    wmma::fragment<wmma::matrix_b, 16, 16, 16, __half, wmma::col_major> bf;
                    wmma::load_matrix_sync(bf, &Ks[(wk * 32 + n * 16) * QLD + kk * 16], QLD);
                    wmma::mma_sync(sacc[n], af, bf, sacc[n]);
                }
            }
#pragma unroll
            for (int n = 0; n < 2; n++)
                wmma::store_matrix_sync(&Ss[(wq * 16) * QLD + wk * 32 + n * 16],
                                        sacc[n], QLD, wmma::mem_row_major);
        }
        __syncthreads();

        // ---- online softmax (4 threads/row) ----
        {
            const int row = t >> 2;
            const int g = t & 3;
            float* srow = &Ss[row * QLD + g * 16];
            __half* prow = &Ps[row * QLD + g * 16];
            const int gq = qb * 64 + row;
            const int cbase = jb * 64 + g * 16;
            float sv[16];
            float mx = -1e30f;
#pragma unroll
            for (int j = 0; j < 16; j++) {
                float xv = srow[j];
                if (jb == qb && cbase + j > gq) xv = -1e30f;
                sv[j] = xv;
                mx = fmaxf(mx, xv);
            }
            mx = fmaxf(mx, __shfl_xor_sync(0xffffffffu, mx, 1));
            mx = fmaxf(mx, __shfl_xor_sync(0xffffffffu, mx, 2));
            float mold = mrow[row];
            float mn = fmaxf(mold, mx);
            float a = __expf(mold - mn);
            float sum = 0.f;
#pragma unroll
            for (int j = 0; j < 16; j++) {
                float p = __expf(sv[j] - mn);
                prow[j] = __float2half(p);
                sum += p;
            }
            sum += __shfl_xor_sync(0xffffffffu, sum, 1);
            sum += __shfl_xor_sync(0xffffffffu, sum, 2);
            if (g == 0) {
                mrow[row] = mn;
                lrow[row] = lrow[row] * a + sum;
                arow[row] = a;
            }
        }
        __syncthreads();

        // ---- PV = P @ V ; Os = a*Os + PV ----
        wmma::fragment<wmma::accumulator, 16, 16, 16, float> oacc[2];
#pragma unroll
        for (int n = 0; n < 2; n++) wmma::fill_fragment(oacc[n], 0.0f);
#pragma unroll
        for (int kk = 0; kk < 4; kk++) {
            wmma::fragment<wmma::matrix_a, 16, 16, 16, __half, wmma::row_major> af;
            wmma::load_matrix_sync(af, &Ps[(wq * 16) * QLD + kk * 16], QLD);
#pragma unroll
            for (int n = 0; n < 2; n++) {
                wmma::fragment<wmma::matrix_b, 16, 16, 16, __half, wmma::row_major> bf;
                wmma::load_matrix_sync(bf, &Vs[(kk * 16) * QLD + wk * 32 + n * 16], QLD);
                wmma::mma_sync(oacc[n], af, bf, oacc[n]);
            }
        }
#pragma unroll
        for (int n = 0; n < 2; n++)
            wmma::store_matrix_sync(&Ss[(wq * 16) * QLD + wk * 32 + n * 16],
                                    oacc[n], QLD, wmma::mem_row_major);
        __syncthreads();

#pragma unroll
        for (int i = 0; i < 4; i++) {
            int idx = t + i * 256;
            int r = idx >> 4;
            int c = (idx & 15) << 2;
            float a = arow[r];
            float* od = &Os[r * QLD + c];
            const float* pd = &Ss[r * QLD + c];
            od[0] = od[0] * a + pd[0];
            od[1] = od[1] * a + pd[1];
            od[2] = od[2] * a + pd[2];
            od[3] = od[3] * a + pd[3];
        }
    }
    __syncthreads();

#pragma unroll
    for (int i = 0; i < 4; i++) {
        int idx = t + i * 256;
        int r = idx >> 4;
        int c = (idx & 15) << 2;
        float inv = 1.0f / lrow[r];
        const float* od = &Os[r * QLD + c];
        store_half4(out + (size_t)(b * kS + qb * 64 + r) * kD + h * kHD + c,
                    od[0] * inv, od[1] * inv, od[2] * inv, od[3] * inv);
    }
}

// ---------------- launch ----------------
extern "C" void kernel_launch(void* const* d_in, const int* in_sizes, int n_in,
                              void* d_out, int out_size)
{
    const float* x    = (const float*)d_in[0];
    const float* Wq   = (const float*)d_in[1];
    const float* bq   = (const float*)d_in[2];
    const float* Wk   = (const float*)d_in[3];
    const float* bk   = (const float*)d_in[4];
    const float* Wv   = (const float*)d_in[5];
    const float* bv   = (const float*)d_in[6];
    const float* Wo   = (const float*)d_in[7];
    const float* bo   = (const float*)d_in[8];
    const float* W1   = (const float*)d_in[9];
    const float* b1   = (const float*)d_in[10];
    const float* W2   = (const float*)d_in[11];
    const float* b2   = (const float*)d_in[12];
    const float* ln1g = (const float*)d_in[13];
    const float* ln1b = (const float*)d_in[14];
    const float* ln2g = (const float*)d_in[15];
    const float* ln2b = (const float*)d_in[16];
    float* out = (float*)d_out;

    __half *h1, *wqkv, *attn, *ff1, *wo, *w1, *w2;
    float *bqkv, *qkv, *x2;
    cudaGetSymbolAddress((void**)&h1,   g_h1);
    cudaGetSymbolAddress((void**)&wqkv, g_wqkv);
    cudaGetSymbolAddress((void**)&bqkv, g_bqkv);
    cudaGetSymbolAddress((void**)&qkv,  g_qkv);
    cudaGetSymbolAddress((void**)&attn, g_attn);
    cudaGetSymbolAddress((void**)&x2,   g_x2);
    cudaGetSymbolAddress((void**)&ff1,  g_ff1);
    cudaGetSymbolAddress((void**)&wo,   g_wo);
    cudaGetSymbolAddress((void**)&w1,   g_w1);
    cudaGetSymbolAddress((void**)&w2,   g_w2);

    cudaFuncSetAttribute(attn_kernel, cudaFuncAttributeMaxDynamicSharedMemorySize, ATT_SMEM);
    cudaFuncSetAttribute(gemm_h, cudaFuncAttributeMaxDynamicSharedMemorySize, GEMM_SMEM);

    // 0. convert weights to fp16 once
    tohalf_kernel<<<(kD * kD / 4 + 255) / 256, 256>>>(Wo, wo, kD * kD / 4);
    tohalf_kernel<<<(kD * kFF / 4 + 255) / 256, 256>>>(W1, w1, kD * kFF / 4);
    tohalf_kernel<<<(kFF * kD / 4 + 255) / 256, 256>>>(W2, w2, kFF * kD / 4);
    // 1. pack QKV weights/biases
    pack_qkv_kernel<<<(kD * kQKV + 255) / 256, 256>>>(Wq, Wk, Wv, bq, bk, bv);
    // 2. LN1 -> fp16
    ln_kernel<<<kM, 256>>>(x, ln1g, ln1b, h1);
    // 3. QKV projection (+bias) -> fp32 qkv
    gemm_h<<<dim3(kQKV / GBN, kM / GBM), 256, GEMM_SMEM>>>(h1, wqkv, qkv, nullptr, bqkv, nullptr,
                                                           kM, kQKV, kD, 0, 0);
    // 4. attention -> fp16 attn
    attn_kernel<<<dim3(kS / 64, kB * kH), 256, ATT_SMEM>>>(qkv, attn);
    // 5. output projection (+bias+residual) -> fp32 x2
    gemm_h<<<dim3(kD / GBN, kM / GBM), 256, GEMM_SMEM>>>(attn, wo, x2, nullptr, bo, x,
                                                         kM, kD, kD, 1, 0);
    // 6. LN2 -> fp16
    ln_kernel<<<kM, 256>>>(x2, ln2g, ln2b, h1);
    // 7. FFN up (+bias+gelu) -> fp16 ff1
    gemm_h<<<dim3(kFF / GBN, kM / GBM), 256, GEMM_SMEM>>>(h1, w1, nullptr, ff1, b1, nullptr,
                                                          kM, kFF, kD, 2, 1);
    // 8. FFN down (+bias+gelu+residual) -> fp32 out
    gemm_h<<<dim3(kD / GBN, kM / GBM), 256, GEMM_SMEM>>>(ff1, w2, out, nullptr, b2, x2,
                                                         kM, kD, kFF, 3, 0);
}

// round 10
// speedup vs baseline: 4.2173x; 1.0297x over previous
#include <cuda_runtime.h>
#include <cuda_fp16.h>
#include <mma.h>
#include <cmath>
#include <cstdint>

using namespace nvcuda;

constexpr int kB = 4, kS = 2048, kD = 1024, kH = 16, kHD = 64, kFF = 4096;
constexpr int kM = kB * kS;          // 8192 rows
constexpr int kQKV = 3 * kD;         // 3072

// ---------------- scratch (static device globals; no allocation) ----------------
__device__ __half g_h1[(size_t)kM * kD];        // LN out (fp16)
__device__ __half g_wqkv[(size_t)kD * kQKV];    // packed QKV weight (fp16)
__device__ float  g_bqkv[kQKV];
__device__ __half g_qkv[(size_t)kM * kQKV];     // q|k|v fp16
__device__ __half g_attn[(size_t)kM * kD];      // attention out (fp16)
__device__ float  g_x2[(size_t)kM * kD];        // residual after attention (fp32)
__device__ __half g_ff1[(size_t)kM * kFF];      // FFN hidden (fp16)
__device__ __half g_wo[(size_t)kD * kD];
__device__ __half g_w1[(size_t)kD * kFF];
__device__ __half g_w2[(size_t)kFF * kD];

// ---------------- helpers ----------------
__device__ __forceinline__ void cp_async16(void* smem, const void* gmem)
{
    unsigned int s = (unsigned int)__cvta_generic_to_shared(smem);
    asm volatile("cp.async.cg.shared.global [%0], [%1], 16;\n" :: "r"(s), "l"(gmem));
}

__device__ __forceinline__ float gelu_exact(float x)
{
    return 0.5f * x * (1.0f + erff(x * 0.70710678118654752f));
}

__device__ __forceinline__ void store_half4(__half* dst, float a, float b, float c, float d)
{
    __half2 h0 = __floats2half2_rn(a, b);
    __half2 h1 = __floats2half2_rn(c, d);
    uint2 u;
    u.x = *reinterpret_cast<unsigned int*>(&h0);
    u.y = *reinterpret_cast<unsigned int*>(&h1);
    *reinterpret_cast<uint2*>(dst) = u;
}

// ---------------- fp32 -> fp16 weight conversion ----------------
__global__ void tohalf_kernel(const float* __restrict__ src, __half* __restrict__ dst, int n4)
{
    int i = blockIdx.x * blockDim.x + threadIdx.x;
    if (i >= n4) return;
    float4 v = reinterpret_cast<const float4*>(src)[i];
    store_half4(dst + (size_t)i * 4, v.x, v.y, v.z, v.w);
}

// ---------------- weight/bias packing (fp16) ----------------
__global__ void pack_qkv_kernel(const float* __restrict__ Wq, const float* __restrict__ Wk,
                                const float* __restrict__ Wv, const float* __restrict__ bq,
                                const float* __restrict__ bk, const float* __restrict__ bv)
{
    int idx = blockIdx.x * blockDim.x + threadIdx.x;
    const int total = kD * kQKV;
    if (idx >= total) return;
    int d = idx / kQKV;
    int n = idx % kQKV;
    int sect = n / kD;
    int c = n % kD;
    int h = c / kHD;
    int e = c % kHD;
    const float* W = (sect == 0) ? Wq : (sect == 1) ? Wk : Wv;
    g_wqkv[idx] = __float2half(W[((size_t)h * kD + d) * kHD + e]);
    if (idx < kQKV) {
        const float* bb = (idx < kD) ? bq : (idx < 2 * kD) ? bk : bv;
        g_bqkv[idx] = bb[idx % kD];
    }
}

// ---------------- LayerNorm (one block per row; fp16 output) ----------------
__global__ void ln_kernel(const float* __restrict__ x, const float* __restrict__ g,
                          const float* __restrict__ beta, __half* __restrict__ o)
{
    __shared__ float red[8];
    int row = blockIdx.x;
    int t = threadIdx.x;  // 256
    float4 v = reinterpret_cast<const float4*>(x + (size_t)row * kD)[t];
    float s = v.x + v.y + v.z + v.w;
#pragma unroll
    for (int off = 16; off; off >>= 1) s += __shfl_xor_sync(0xffffffffu, s, off);
    if ((t & 31) == 0) red[t >> 5] = s;
    __syncthreads();
    float tot = 0.f;
#pragma unroll
    for (int i = 0; i < 8; i++) tot += red[i];
    float mu = tot * (1.0f / kD);
    __syncthreads();
    float d0 = v.x - mu, d1 = v.y - mu, d2 = v.z - mu, d3 = v.w - mu;
    float s2 = d0 * d0 + d1 * d1 + d2 * d2 + d3 * d3;
#pragma unroll
    for (int off = 16; off; off >>= 1) s2 += __shfl_xor_sync(0xffffffffu, s2, off);
    if ((t & 31) == 0) red[t >> 5] = s2;
    __syncthreads();
    float tot2 = 0.f;
#pragma unroll
    for (int i = 0; i < 8; i++) tot2 += red[i];
    float inv = rsqrtf(tot2 * (1.0f / kD) + 1e-5f);
    float4 gg = reinterpret_cast<const float4*>(g)[t];
    float4 bb = reinterpret_cast<const float4*>(beta)[t];
    store_half4(o + (size_t)row * kD + t * 4,
                d0 * inv * gg.x + bb.x, d1 * inv * gg.y + bb.y,
                d2 * inv * gg.z + bb.z, d3 * inv * gg.w + bb.w);
}

// ---------------- FP16 WMMA GEMM: 128x256 block, 64x64 warp, 4-stage cp.async ----------------
constexpr int GBM = 128, GBN = 256, GBK = 32;
constexpr int NSTAGE = 4;
constexpr int A_LDh = 40;
constexpr int B_LDh = 264;
constexpr int ASZh = GBM * A_LDh;
constexpr int BSZh = GBK * B_LDh;
constexpr int STAGEh = ASZh + BSZh;
constexpr int GEMM_SMEM = NSTAGE * STAGEh * 2;   // 108544 B
constexpr int C_LDf = 264;

__global__ __launch_bounds__(256, 1) void gemm_h(const __half* __restrict__ A,
                                                 const __half* __restrict__ Bm,
                                                 float* __restrict__ C32,
                                                 __half* __restrict__ C16,
                                                 const float* __restrict__ bias,
                                                 const float* __restrict__ res,
                                                 int M, int N, int K, int mode, int out16)
{
    extern __shared__ char smc[];

    const int bm = blockIdx.y * GBM;
    const int bn = blockIdx.x * GBN;
    const int t = threadIdx.x;
    const int warp = t >> 5;
    const int wm = warp >> 2;
    const int wn = warp & 3;

    wmma::fragment<wmma::accumulator, 16, 16, 16, float> acc[4][4];
#pragma unroll
    for (int i = 0; i < 4; i++)
#pragma unroll
        for (int j = 0; j < 4; j++) wmma::fill_fragment(acc[i][j], 0.0f);

    const int KT = K / GBK;

    auto load_tile = [&](int kt, int buf) {
        __half* As = reinterpret_cast<__half*>(smc) + buf * STAGEh;
        __half* Bs = As + ASZh;
        const __half* Ab = A + (size_t)bm * K + (size_t)kt * GBK;
        const __half* Bb = Bm + (size_t)kt * GBK * N + bn;
#pragma unroll
        for (int i = 0; i < 2; i++) {
            int ch = t + i * 256;
            int r = ch >> 2;
            int c = (ch & 3) * 8;
            cp_async16(&As[r * A_LDh + c], Ab + (size_t)r * K + c);
        }
#pragma unroll
        for (int i = 0; i < 4; i++) {
            int ch = t + i * 256;
            int r = ch >> 5;
            int c = (ch & 31) * 8;
            cp_async16(&Bs[r * B_LDh + c], Bb + (size_t)r * N + c);
        }
        asm volatile("cp.async.commit_group;\n");
    };

    load_tile(0, 0);
    load_tile(1, 1);
    load_tile(2, 2);

    for (int kt = 0; kt < KT; kt++) {
        const int buf = kt % NSTAGE;
        if (kt + 3 < KT) {
            load_tile(kt + 3, (kt + 3) % NSTAGE);
            asm volatile("cp.async.wait_group 3;\n");
        } else if (kt + 2 < KT) {
            asm volatile("cp.async.wait_group 2;\n");
        } else if (kt + 1 < KT) {
            asm volatile("cp.async.wait_group 1;\n");
        } else {
            asm volatile("cp.async.wait_group 0;\n");
        }
        __syncthreads();

        const __half* As = reinterpret_cast<const __half*>(smc) + buf * STAGEh;
        const __half* Bs = As + ASZh;
#pragma unroll
        for (int kk = 0; kk < 2; kk++) {
            wmma::fragment<wmma::matrix_a, 16, 16, 16, __half, wmma::row_major> af[4];
            wmma::fragment<wmma::matrix_b, 16, 16, 16, __half, wmma::row_major> bf[4];
#pragma unroll
            for (int i = 0; i < 4; i++)
                wmma::load_matrix_sync(af[i], &As[(wm * 64 + i * 16) * A_LDh + kk * 16], A_LDh);
#pragma unroll
            for (int j = 0; j < 4; j++)
                wmma::load_matrix_sync(bf[j], &Bs[(kk * 16) * B_LDh + wn * 64 + j * 16], B_LDh);
#pragma unroll
            for (int i = 0; i < 4; i++)
#pragma unroll
                for (int j = 0; j < 4; j++)
                    wmma::mma_sync(acc[i][j], af[i], bf[j], acc[i][j]);
        }
        __syncthreads();
    }

    // ---- epilogue in fragments ----
    float* smf = reinterpret_cast<float*>(smc);

#pragma unroll
    for (int i = 0; i < 16; i++) {
        int idx = t + i * 256;
        int r = idx >> 8;
        int c = idx & 255;
        smf[r * C_LDf + c] = bias[bn + c];
    }
    __syncthreads();

    wmma::fragment<wmma::accumulator, 16, 16, 16, float> bfr[4];
#pragma unroll
    for (int j = 0; j < 4; j++)
        wmma::load_matrix_sync(bfr[j], &smf[wn * 64 + j * 16], C_LDf, wmma::mem_row_major);
    __syncthreads();

#pragma unroll
    for (int i = 0; i < 4; i++)
#pragma unroll
        for (int j = 0; j < 4; j++) {
#pragma unroll
            for (int e = 0; e < acc[i][j].num_elements; e++) {
                float v = acc[i][j].x[e] + bfr[j].x[e];
                if (mode >= 2) v = gelu_exact(v);
                acc[i][j].x[e] = v;
            }
            if (mode == 1 || mode == 3) {
                wmma::fragment<wmma::accumulator, 16, 16, 16, float> rf;
                wmma::load_matrix_sync(rf, res + (size_t)(bm + wm * 64 + i * 16) * N + bn + wn * 64 + j * 16,
                                       N, wmma::mem_row_major);
#pragma unroll
                for (int e = 0; e < acc[i][j].num_elements; e++)
                    acc[i][j].x[e] += rf.x[e];
            }
        }

    if (!out16) {
#pragma unroll
        for (int i = 0; i < 4; i++)
#pragma unroll
            for (int j = 0; j < 4; j++)
                wmma::store_matrix_sync(C32 + (size_t)(bm + wm * 64 + i * 16) * N + bn + wn * 64 + j * 16,
                                        acc[i][j], N, wmma::mem_row_major);
    } else {
#pragma unroll
        for (int pass = 0; pass < 2; pass++) {
#pragma unroll
            for (int ii = 0; ii < 2; ii++) {
                int i = pass * 2 + ii;
                int sr = wm * 32 + ii * 16;
#pragma unroll
                for (int j = 0; j < 4; j++)
                    wmma::store_matrix_sync(&smf[sr * C_LDf + wn * 64 + j * 16],
                                            acc[i][j], C_LDf, wmma::mem_row_major);
            }
            __syncthreads();
#pragma unroll
            for (int it = 0; it < 16; it++) {
                int idx = t + it * 256;
                int sr = idx >> 6;
                int c4 = (idx & 63) << 2;
                int gr = (sr & 31) + (sr >> 5) * 64 + pass * 32;
                const float* src = &smf[sr * C_LDf + c4];
                store_half4(C16 + (size_t)(bm + gr) * N + bn + c4,
                            src[0], src[1], src[2], src[3]);
            }
            __syncthreads();
        }
    }
}

// ---------------- FP16 WMMA flash attention (causal, cp.async K/V double-buffer) ----------------
constexpr int QLD = 72;   // half stride (144B, 16B-aligned)
constexpr int TILEH = 64 * QLD;                 // halfs per tile
constexpr int ATT_SMEM = 6 * TILEH * 2 + (2 * 64 * 72 + 3 * 64) * 4;   // 92928 B

__global__ __launch_bounds__(256, 2) void attn_kernel(const __half* __restrict__ qkv,
                                                      __half* __restrict__ out)
{
    extern __shared__ char smc[];
    __half* Qs = reinterpret_cast<__half*>(smc);
    __half* Ks = Qs + TILEH;            // [2][TILEH]
    __half* Vs = Ks + 2 * TILEH;        // [2][TILEH]
    __half* Ps = Vs + 2 * TILEH;
    float*  Ss = reinterpret_cast<float*>(Ps + TILEH);
    float*  Os = Ss + 64 * 72;
    float*  mrow = Os + 64 * 72;
    float*  lrow = mrow + 64;
    float*  arow = lrow + 64;

    const int qb = blockIdx.x;
    const int bh = blockIdx.y;
    const int b = bh >> 4;
    const int h = bh & 15;
    const int t = threadIdx.x;
    const int warp = t >> 5;
    const int wq = warp >> 1;
    const int wk = warp & 1;

    const __half* base = qkv + (size_t)b * kS * kQKV + h * kHD;

    auto load_kv = [&](int jb, int buf) {
        __half* kd = Ks + buf * TILEH;
        __half* vd = Vs + buf * TILEH;
#pragma unroll
        for (int i = 0; i < 2; i++) {
            int ch = t + i * 256;          // 0..511: 64 rows x 8 chunks
            int r = ch >> 3;
            int c = (ch & 7) * 8;
            const __half* kr = base + (size_t)(jb * 64 + r) * kQKV + kD + c;
            cp_async16(&kd[r * QLD + c], kr);
            cp_async16(&vd[r * QLD + c], kr + kD);
        }
        asm volatile("cp.async.commit_group;\n");
    };

    // Q async load (grouped with KV stage 0)
#pragma unroll
    for (int i = 0; i < 2; i++) {
        int ch = t + i * 256;
        int r = ch >> 3;
        int c = (ch & 7) * 8;
        cp_async16(&Qs[r * QLD + c], base + (size_t)(qb * 64 + r) * kQKV + c);
    }
    load_kv(0, 0);

    for (int i = t; i < 64 * 72; i += 256) Os[i] = 0.f;
    if (t < 64) { mrow[t] = -1e30f; lrow[t] = 0.f; }

    int buf = 0;
    for (int jb = 0; jb <= qb; jb++) {
        if (jb + 1 <= qb) {
            load_kv(jb + 1, buf ^ 1);
            asm volatile("cp.async.wait_group 1;\n");
        } else {
            asm volatile("cp.async.wait_group 0;\n");
        }
        __syncthreads();

        const __half* Kb = Ks + buf * TILEH;
        const __half* Vb = Vs + buf * TILEH;

        // ---- S = Q @ K^T ----
        {
            wmma::fragment<wmma::accumulator, 16, 16, 16, float> sacc[2];
#pragma unroll
            for (int n = 0; n < 2; n++) wmma::fill_fragment(sacc[n], 0.0f);
#pragma unroll
            for (int kk = 0; kk < 4; kk++) {
                wmma::fragment<wmma::matrix_a, 16, 16, 16, __half, wmma::row_major> af;
                wmma::load_matrix_sync(af, &Qs[(wq * 16) * QLD + kk * 16], QLD);
#pragma unroll
                for (int n = 0; n < 2; n++) {
                    wmma::fragment<wmma::matrix_b, 16, 16, 16, __half, wmma::col_major> bf;
                    wmma::load_matrix_sync(bf, &Kb[(wk * 32 + n * 16) * QLD + kk * 16], QLD);
                    wmma::mma_sync(sacc[n], af, bf, sacc[n]);
                }
            }
#pragma unroll
            for (int n = 0; n < 2; n++)
                wmma::store_matrix_sync(&Ss[(wq * 16) * 72 + wk * 32 + n * 16],
                                        sacc[n], 72, wmma::mem_row_major);
        }
        __syncthreads();

        // ---- online softmax (4 threads/row); scale 1/8 applied here ----
        {
            const int row = t >> 2;
            const int g = t & 3;
            float* srow = &Ss[row * 72 + g * 16];
            __half* prow = &Ps[row * QLD + g * 16];
            const int gq = qb * 64 + row;
            const int cbase = jb * 64 + g * 16;
            float sv[16];
            float mx = -1e30f;
#pragma unroll
            for (int j = 0; j < 16; j++) {
                float xv = srow[j] * 0.125f;
                if (jb == qb && cbase + j > gq) xv = -1e30f;
                sv[j] = xv;
                mx = fmaxf(mx, xv);
            }
            mx = fmaxf(mx, __shfl_xor_sync(0xffffffffu, mx, 1));
            mx = fmaxf(mx, __shfl_xor_sync(0xffffffffu, mx, 2));
            float mold = mrow[row];
            float mn = fmaxf(mold, mx);
            float a = __expf(mold - mn);
            float sum = 0.f;
#pragma unroll
            for (int j = 0; j < 16; j++) {
                float p = __expf(sv[j] - mn);
                prow[j] = __float2half(p);
                sum += p;
            }
            sum += __shfl_xor_sync(0xffffffffu, sum, 1);
            sum += __shfl_xor_sync(0xffffffffu, sum, 2);
            if (g == 0) {
                mrow[row] = mn;
                lrow[row] = lrow[row] * a + sum;
                arow[row] = a;
            }
        }
        __syncthreads();

        // ---- PV = P @ V ; Os = a*Os + PV ----
        wmma::fragment<wmma::accumulator, 16, 16, 16, float> oacc[2];
#pragma unroll
        for (int n = 0; n < 2; n++) wmma::fill_fragment(oacc[n], 0.0f);
#pragma unroll
        for (int kk = 0; kk < 4; kk++) {
            wmma::fragment<wmma::matrix_a, 16, 16, 16, __half, wmma::row_major> af;
            wmma::load_matrix_sync(af, &Ps[(wq * 16) * QLD + kk * 16], QLD);
#pragma unroll
            for (int n = 0; n < 2; n++) {
                wmma::fragment<wmma::matrix_b, 16, 16, 16, __half, wmma::row_major> bf;
                wmma::load_matrix_sync(bf, &Vb[(kk * 16) * QLD + wk * 32 + n * 16], QLD);
                wmma::mma_sync(oacc[n], af, bf, oacc[n]);
            }
        }
#pragma unroll
        for (int n = 0; n < 2; n++)
            wmma::store_matrix_sync(&Ss[(wq * 16) * 72 + wk * 32 + n * 16],
                                    oacc[n], 72, wmma::mem_row_major);
        __syncthreads();

#pragma unroll
        for (int i = 0; i < 4; i++) {
            int idx = t + i * 256;
            int r = idx >> 4;
            int c = (idx & 15) << 2;
            float a = arow[r];
            float* od = &Os[r * 72 + c];
            const float* pd = &Ss[r * 72 + c];
            od[0] = od[0] * a + pd[0];
            od[1] = od[1] * a + pd[1];
            od[2] = od[2] * a + pd[2];
            od[3] = od[3] * a + pd[3];
        }
        __syncthreads();
        buf ^= 1;
    }

#pragma unroll
    for (int i = 0; i < 4; i++) {
        int idx = t + i * 256;
        int r = idx >> 4;
        int c = (idx & 15) << 2;
        float inv = 1.0f / lrow[r];
        const float* od = &Os[r * 72 + c];
        store_half4(out + (size_t)(b * kS + qb * 64 + r) * kD + h * kHD + c,
                    od[0] * inv, od[1] * inv, od[2] * inv, od[3] * inv);
    }
}

// ---------------- launch ----------------
extern "C" void kernel_launch(void* const* d_in, const int* in_sizes, int n_in,
                              void* d_out, int out_size)
{
    const float* x    = (const float*)d_in[0];
    const float* Wq   = (const float*)d_in[1];
    const float* bq   = (const float*)d_in[2];
    const float* Wk   = (const float*)d_in[3];
    const float* bk   = (const float*)d_in[4];
    const float* Wv   = (const float*)d_in[5];
    const float* bv   = (const float*)d_in[6];
    const float* Wo   = (const float*)d_in[7];
    const float* bo   = (const float*)d_in[8];
    const float* W1   = (const float*)d_in[9];
    const float* b1   = (const float*)d_in[10];
    const float* W2   = (const float*)d_in[11];
    const float* b2   = (const float*)d_in[12];
    const float* ln1g = (const float*)d_in[13];
    const float* ln1b = (const float*)d_in[14];
    const float* ln2g = (const float*)d_in[15];
    const float* ln2b = (const float*)d_in[16];
    float* out = (float*)d_out;

    __half *h1, *wqkv, *qkv, *attn, *ff1, *wo, *w1, *w2;
    float *bqkv, *x2;
    cudaGetSymbolAddress((void**)&h1,   g_h1);
    cudaGetSymbolAddress((void**)&wqkv, g_wqkv);
    cudaGetSymbolAddress((void**)&bqkv, g_bqkv);
    cudaGetSymbolAddress((void**)&qkv,  g_qkv);
    cudaGetSymbolAddress((void**)&attn, g_attn);
    cudaGetSymbolAddress((void**)&x2,   g_x2);
    cudaGetSymbolAddress((void**)&ff1,  g_ff1);
    cudaGetSymbolAddress((void**)&wo,   g_wo);
    cudaGetSymbolAddress((void**)&w1,   g_w1);
    cudaGetSymbolAddress((void**)&w2,   g_w2);

    cudaFuncSetAttribute(attn_kernel, cudaFuncAttributeMaxDynamicSharedMemorySize, ATT_SMEM);
    cudaFuncSetAttribute(gemm_h, cudaFuncAttributeMaxDynamicSharedMemorySize, GEMM_SMEM);

    // 0. convert weights to fp16 once
    tohalf_kernel<<<(kD * kD / 4 + 255) / 256, 256>>>(Wo, wo, kD * kD / 4);
    tohalf_kernel<<<(kD * kFF / 4 + 255) / 256, 256>>>(W1, w1, kD * kFF / 4);
    tohalf_kernel<<<(kFF * kD / 4 + 255) / 256, 256>>>(W2, w2, kFF * kD / 4);
    // 1. pack QKV weights/biases
    pack_qkv_kernel<<<(kD * kQKV + 255) / 256, 256>>>(Wq, Wk, Wv, bq, bk, bv);
    // 2. LN1 -> fp16
    ln_kernel<<<kM, 256>>>(x, ln1g, ln1b, h1);
    // 3. QKV projection (+bias) -> fp16 qkv
    gemm_h<<<dim3(kQKV / GBN, kM / GBM), 256, GEMM_SMEM>>>(h1, wqkv, nullptr, qkv, bqkv, nullptr,
                                                           kM, kQKV, kD, 0, 1);
    // 4. attention -> fp16 attn
    attn_kernel<<<dim3(kS / 64, kB * kH), 256, ATT_SMEM>>>(qkv, attn);
    // 5. output projection (+bias+residual) -> fp32 x2
    gemm_h<<<dim3(kD / GBN, kM / GBM), 256, GEMM_SMEM>>>(attn, wo, x2, nullptr, bo, x,
                                                         kM, kD, kD, 1, 0);
    // 6. LN2 -> fp16
    ln_kernel<<<kM, 256>>>(x2, ln2g, ln2b, h1);
    // 7. FFN up (+bias+gelu) -> fp16 ff1
    gemm_h<<<dim3(kFF / GBN, kM / GBM), 256, GEMM_SMEM>>>(h1, w1, nullptr, ff1, b1, nullptr,
                                                          kM, kFF, kD, 2, 1);
    // 8. FFN down (+bias+gelu+residual) -> fp32 out
    gemm_h<<<dim3(kD / GBN, kM / GBM), 256, GEMM_SMEM>>>(ff1, w2, out, nullptr, b2, x2,
                                                         kM, kD, kFF, 3, 0);
}

// round 11
// speedup vs baseline: 4.7906x; 1.1359x over previous
#include <cuda_runtime.h>
#include <cuda_fp16.h>
#include <mma.h>
#include <cmath>
#include <cstdint>

using namespace nvcuda;

constexpr int kB = 4, kS = 2048, kD = 1024, kH = 16, kHD = 64, kFF = 4096;
constexpr int kM = kB * kS;
constexpr int kQKV = 3 * kD;

// ---------------- scratch ----------------
__device__ __half g_h1[(size_t)kM * kD];
__device__ __half g_wqkv[(size_t)kD * kQKV];
__device__ float  g_bqkv[kQKV];
__device__ __half g_qkv[(size_t)kM * kQKV];
__device__ __half g_attn[(size_t)kM * kD];
__device__ float  g_x2[(size_t)kM * kD];
__device__ __half g_ff1[(size_t)kM * kFF];
__device__ __half g_wo[(size_t)kD * kD];
__device__ __half g_w1[(size_t)kD * kFF];
__device__ __half g_w2[(size_t)kFF * kD];

// ---------------- helpers ----------------
__device__ __forceinline__ void cp_async16(void* smem, const void* gmem)
{
    unsigned int s = (unsigned int)__cvta_generic_to_shared(smem);
    asm volatile("cp.async.cg.shared.global [%0], [%1], 16;\n" :: "r"(s), "l"(gmem));
}

__device__ __forceinline__ float gelu_exact(float x)
{
    return 0.5f * x * (1.0f + erff(x * 0.70710678118654752f));
}

__device__ __forceinline__ void store_half4(__half* dst, float a, float b, float c, float d)
{
    __half2 h0 = __floats2half2_rn(a, b);
    __half2 h1 = __floats2half2_rn(c, d);
    uint2 u;
    u.x = *reinterpret_cast<unsigned int*>(&h0);
    u.y = *reinterpret_cast<unsigned int*>(&h1);
    *reinterpret_cast<uint2*>(dst) = u;
}

__device__ __forceinline__ unsigned int pack_h2(float a, float b)
{
    __half2 h = __floats2half2_rn(a, b);
    return *reinterpret_cast<unsigned int*>(&h);
}

#define LDM_X4(r0, r1, r2, r3, addr) \
    asm volatile("ldmatrix.sync.aligned.m8n8.x4.shared.b16 {%0,%1,%2,%3}, [%4];" \
        : "=r"(r0), "=r"(r1), "=r"(r2), "=r"(r3) : "r"(addr))

#define LDM_X4_T(r0, r1, r2, r3, addr) \
    asm volatile("ldmatrix.sync.aligned.m8n8.x4.trans.shared.b16 {%0,%1,%2,%3}, [%4];" \
        : "=r"(r0), "=r"(r1), "=r"(r2), "=r"(r3) : "r"(addr))

#define MMA16816(c, a0, a1, a2, a3, b0, b1) \
    asm volatile("mma.sync.aligned.m16n8k16.row.col.f32.f16.f16.f32 " \
        "{%0,%1,%2,%3}, {%4,%5,%6,%7}, {%8,%9}, {%0,%1,%2,%3};" \
        : "+f"(c[0]), "+f"(c[1]), "+f"(c[2]), "+f"(c[3]) \
        : "r"(a0), "r"(a1), "r"(a2), "r"(a3), "r"(b0), "r"(b1))

// ---------------- fp32 -> fp16 weight conversion ----------------
__global__ void tohalf_kernel(const float* __restrict__ src, __half* __restrict__ dst, int n4)
{
    int i = blockIdx.x * blockDim.x + threadIdx.x;
    if (i >= n4) return;
    float4 v = reinterpret_cast<const float4*>(src)[i];
    store_half4(dst + (size_t)i * 4, v.x, v.y, v.z, v.w);
}

// ---------------- weight/bias packing ----------------
__global__ void pack_qkv_kernel(const float* __restrict__ Wq, const float* __restrict__ Wk,
                                const float* __restrict__ Wv, const float* __restrict__ bq,
                                const float* __restrict__ bk, const float* __restrict__ bv)
{
    int idx = blockIdx.x * blockDim.x + threadIdx.x;
    const int total = kD * kQKV;
    if (idx >= total) return;
    int d = idx / kQKV;
    int n = idx % kQKV;
    int sect = n / kD;
    int c = n % kD;
    int h = c / kHD;
    int e = c % kHD;
    const float* W = (sect == 0) ? Wq : (sect == 1) ? Wk : Wv;
    g_wqkv[idx] = __float2half(W[((size_t)h * kD + d) * kHD + e]);
    if (idx < kQKV) {
        const float* bb = (idx < kD) ? bq : (idx < 2 * kD) ? bk : bv;
        g_bqkv[idx] = bb[idx % kD];
    }
}

// ---------------- LayerNorm ----------------
__global__ void ln_kernel(const float* __restrict__ x, const float* __restrict__ g,
                          const float* __restrict__ beta, __half* __restrict__ o)
{
    __shared__ float red[8];
    int row = blockIdx.x;
    int t = threadIdx.x;
    float4 v = reinterpret_cast<const float4*>(x + (size_t)row * kD)[t];
    float s = v.x + v.y + v.z + v.w;
#pragma unroll
    for (int off = 16; off; off >>= 1) s += __shfl_xor_sync(0xffffffffu, s, off);
    if ((t & 31) == 0) red[t >> 5] = s;
    __syncthreads();
    float tot = 0.f;
#pragma unroll
    for (int i = 0; i < 8; i++) tot += red[i];
    float mu = tot * (1.0f / kD);
    __syncthreads();
    float d0 = v.x - mu, d1 = v.y - mu, d2 = v.z - mu, d3 = v.w - mu;
    float s2 = d0 * d0 + d1 * d1 + d2 * d2 + d3 * d3;
#pragma unroll
    for (int off = 16; off; off >>= 1) s2 += __shfl_xor_sync(0xffffffffu, s2, off);
    if ((t & 31) == 0) red[t >> 5] = s2;
    __syncthreads();
    float tot2 = 0.f;
#pragma unroll
    for (int i = 0; i < 8; i++) tot2 += red[i];
    float inv = rsqrtf(tot2 * (1.0f / kD) + 1e-5f);
    float4 gg = reinterpret_cast<const float4*>(g)[t];
    float4 bb = reinterpret_cast<const float4*>(beta)[t];
    store_half4(o + (size_t)row * kD + t * 4,
                d0 * inv * gg.x + bb.x, d1 * inv * gg.y + bb.y,
                d2 * inv * gg.z + bb.z, d3 * inv * gg.w + bb.w);
}

// ---------------- FP16 WMMA GEMM (unchanged from R10) ----------------
constexpr int GBM = 128, GBN = 256, GBK = 32;
constexpr int NSTAGE = 4;
constexpr int A_LDh = 40;
constexpr int B_LDh = 264;
constexpr int ASZh = GBM * A_LDh;
constexpr int BSZh = GBK * B_LDh;
constexpr int STAGEh = ASZh + BSZh;
constexpr int GEMM_SMEM = NSTAGE * STAGEh * 2;
constexpr int C_LDf = 264;

__global__ __launch_bounds__(256, 1) void gemm_h(const __half* __restrict__ A,
                                                 const __half* __restrict__ Bm,
                                                 float* __restrict__ C32,
                                                 __half* __restrict__ C16,
                                                 const float* __restrict__ bias,
                                                 const float* __restrict__ res,
                                                 int M, int N, int K, int mode, int out16)
{
    extern __shared__ char smc[];

    const int bm = blockIdx.y * GBM;
    const int bn = blockIdx.x * GBN;
    const int t = threadIdx.x;
    const int warp = t >> 5;
    const int wm = warp >> 2;
    const int wn = warp & 3;

    wmma::fragment<wmma::accumulator, 16, 16, 16, float> acc[4][4];
#pragma unroll
    for (int i = 0; i < 4; i++)
#pragma unroll
        for (int j = 0; j < 4; j++) wmma::fill_fragment(acc[i][j], 0.0f);

    const int KT = K / GBK;

    auto load_tile = [&](int kt, int buf) {
        __half* As = reinterpret_cast<__half*>(smc) + buf * STAGEh;
        __half* Bs = As + ASZh;
        const __half* Ab = A + (size_t)bm * K + (size_t)kt * GBK;
        const __half* Bb = Bm + (size_t)kt * GBK * N + bn;
#pragma unroll
        for (int i = 0; i < 2; i++) {
            int ch = t + i * 256;
            int r = ch >> 2;
            int c = (ch & 3) * 8;
            cp_async16(&As[r * A_LDh + c], Ab + (size_t)r * K + c);
        }
#pragma unroll
        for (int i = 0; i < 4; i++) {
            int ch = t + i * 256;
            int r = ch >> 5;
            int c = (ch & 31) * 8;
            cp_async16(&Bs[r * B_LDh + c], Bb + (size_t)r * N + c);
        }
        asm volatile("cp.async.commit_group;\n");
    };

    load_tile(0, 0);
    load_tile(1, 1);
    load_tile(2, 2);

    for (int kt = 0; kt < KT; kt++) {
        const int buf = kt % NSTAGE;
        if (kt + 3 < KT) {
            load_tile(kt + 3, (kt + 3) % NSTAGE);
            asm volatile("cp.async.wait_group 3;\n");
        } else if (kt + 2 < KT) {
            asm volatile("cp.async.wait_group 2;\n");
        } else if (kt + 1 < KT) {
            asm volatile("cp.async.wait_group 1;\n");
        } else {
            asm volatile("cp.async.wait_group 0;\n");
        }
        __syncthreads();

        const __half* As = reinterpret_cast<const __half*>(smc) + buf * STAGEh;
        const __half* Bs = As + ASZh;
#pragma unroll
        for (int kk = 0; kk < 2; kk++) {
            wmma::fragment<wmma::matrix_a, 16, 16, 16, __half, wmma::row_major> af[4];
            wmma::fragment<wmma::matrix_b, 16, 16, 16, __half, wmma::row_major> bf[4];
#pragma unroll
            for (int i = 0; i < 4; i++)
                wmma::load_matrix_sync(af[i], &As[(wm * 64 + i * 16) * A_LDh + kk * 16], A_LDh);
#pragma unroll
            for (int j = 0; j < 4; j++)
                wmma::load_matrix_sync(bf[j], &Bs[(kk * 16) * B_LDh + wn * 64 + j * 16], B_LDh);
#pragma unroll
            for (int i = 0; i < 4; i++)
#pragma unroll
                for (int j = 0; j < 4; j++)
                    wmma::mma_sync(acc[i][j], af[i], bf[j], acc[i][j]);
        }
        __syncthreads();
    }

    float* smf = reinterpret_cast<float*>(smc);

#pragma unroll
    for (int i = 0; i < 16; i++) {
        int idx = t + i * 256;
        int r = idx >> 8;
        int c = idx & 255;
        smf[r * C_LDf + c] = bias[bn + c];
    }
    __syncthreads();

    wmma::fragment<wmma::accumulator, 16, 16, 16, float> bfr[4];
#pragma unroll
    for (int j = 0; j < 4; j++)
        wmma::load_matrix_sync(bfr[j], &smf[wn * 64 + j * 16], C_LDf, wmma::mem_row_major);
    __syncthreads();

#pragma unroll
    for (int i = 0; i < 4; i++)
#pragma unroll
        for (int j = 0; j < 4; j++) {
#pragma unroll
            for (int e = 0; e < acc[i][j].num_elements; e++) {
                float v = acc[i][j].x[e] + bfr[j].x[e];
                if (mode >= 2) v = gelu_exact(v);
                acc[i][j].x[e] = v;
            }
            if (mode == 1 || mode == 3) {
                wmma::fragment<wmma::accumulator, 16, 16, 16, float> rf;
                wmma::load_matrix_sync(rf, res + (size_t)(bm + wm * 64 + i * 16) * N + bn + wn * 64 + j * 16,
                                       N, wmma::mem_row_major);
#pragma unroll
                for (int e = 0; e < acc[i][j].num_elements; e++)
                    acc[i][j].x[e] += rf.x[e];
            }
        }

    if (!out16) {
#pragma unroll
        for (int i = 0; i < 4; i++)
#pragma unroll
            for (int j = 0; j < 4; j++)
                wmma::store_matrix_sync(C32 + (size_t)(bm + wm * 64 + i * 16) * N + bn + wn * 64 + j * 16,
                                        acc[i][j], N, wmma::mem_row_major);
    } else {
#pragma unroll
        for (int pass = 0; pass < 2; pass++) {
#pragma unroll
            for (int ii = 0; ii < 2; ii++) {
                int i = pass * 2 + ii;
                int sr = wm * 32 + ii * 16;
#pragma unroll
                for (int j = 0; j < 4; j++)
                    wmma::store_matrix_sync(&smf[sr * C_LDf + wn * 64 + j * 16],
                                            acc[i][j], C_LDf, wmma::mem_row_major);
            }
            __syncthreads();
#pragma unroll
            for (int it = 0; it < 16; it++) {
                int idx = t + it * 256;
                int sr = idx >> 6;
                int c4 = (idx & 63) << 2;
                int gr = (sr & 31) + (sr >> 5) * 64 + pass * 32;
                const float* src = &smf[sr * C_LDf + c4];
                store_half4(C16 + (size_t)(bm + gr) * N + bn + c4,
                            src[0], src[1], src[2], src[3]);
            }
            __syncthreads();
        }
    }
}

// ---------------- FA2-style register-resident flash attention ----------------
constexpr int BQ = 128, BK = 64;
constexpr int QLDh = 72;
constexpr int KVTILE = BK * QLDh;                         // halfs
constexpr int ATT_SMEM = (BQ * QLDh + 4 * KVTILE) * 2;    // 55296 B

__global__ __launch_bounds__(256, 2) void attn_kernel(const __half* __restrict__ qkv,
                                                      __half* __restrict__ out)
{
    extern __shared__ char smc[];
    __half* Qs = reinterpret_cast<__half*>(smc);          // [128][72]
    __half* Ks = Qs + BQ * QLDh;                          // [2][64][72]
    __half* Vs = Ks + 2 * KVTILE;                         // [2][64][72]

    const int qb = (int)gridDim.x - 1 - blockIdx.x;       // heavy blocks first
    const int bh = blockIdx.y;
    const int b = bh >> 4, h = bh & 15;
    const int t = threadIdx.x;
    const int w = t >> 5, lane = t & 31;

    const __half* base = qkv + (size_t)b * kS * kQKV + h * kHD;

    // Q load (group 0)
#pragma unroll
    for (int i = 0; i < 4; i++) {
        int ch = t + i * 256;
        int r = ch >> 3, c = (ch & 7) * 8;
        cp_async16(&Qs[r * QLDh + c], base + (size_t)(qb * BQ + r) * kQKV + c);
    }
    asm volatile("cp.async.commit_group;\n");

    auto load_kv = [&](int jb, int buf) {
        __half* kd = Ks + buf * KVTILE;
        __half* vd = Vs + buf * KVTILE;
#pragma unroll
        for (int i = 0; i < 2; i++) {
            int ch = t + i * 256;
            int r = ch >> 3, c = (ch & 7) * 8;
            const __half* kr = base + (size_t)(jb * BK + r) * kQKV + kD + c;
            cp_async16(&kd[r * QLDh + c], kr);
            cp_async16(&vd[r * QLDh + c], kr + kD);
        }
        asm volatile("cp.async.commit_group;\n");
    };

    const int jmax = 2 * qb + 1;
    load_kv(0, 0);
    load_kv(1, 1);

    const int qr0 = w * 16;
    const int growbase = qb * BQ + qr0;
    const int grmax = growbase + 15;
    const int grow0 = growbase + (lane >> 2);

    uint32_t qa[4][4];
    float oacc[8][4];
#pragma unroll
    for (int nt = 0; nt < 8; nt++)
#pragma unroll
        for (int e = 0; e < 4; e++) oacc[nt][e] = 0.f;
    float m0 = -1e30f, m1 = -1e30f, l0 = 0.f, l1 = 0.f;

    for (int jb = 0; jb <= jmax; jb++) {
        const int buf = jb & 1;
        if (jb >= 1 && jb + 1 <= jmax) load_kv(jb + 1, (jb + 1) & 1);
        if (jb + 1 <= jmax) {
            asm volatile("cp.async.wait_group 1;\n");
        } else {
            asm volatile("cp.async.wait_group 0;\n");
        }
        __syncthreads();

        if (jb == 0) {
            // load Q fragments once
#pragma unroll
            for (int kk = 0; kk < 4; kk++) {
                unsigned int addr = (unsigned int)__cvta_generic_to_shared(
                    &Qs[(qr0 + (lane & 15)) * QLDh + kk * 16 + (lane >> 4) * 8]);
                LDM_X4(qa[kk][0], qa[kk][1], qa[kk][2], qa[kk][3], addr);
            }
        }

        if (jb * BK <= grmax) {   // warp-level skip of fully masked tiles
            const __half* Kb = Ks + buf * KVTILE;
            const __half* Vb = Vs + buf * KVTILE;

            // ---- S = Q @ K^T ----
            float sacc[8][4];
#pragma unroll
            for (int nt = 0; nt < 8; nt++) {
#pragma unroll
                for (int e = 0; e < 4; e++) sacc[nt][e] = 0.f;
                const int n0 = nt * 8;
                uint32_t kb[8];
                unsigned int ka0 = (unsigned int)__cvta_generic_to_shared(
                    &Kb[(n0 + (lane & 7)) * QLDh + (lane >> 3) * 8]);
                LDM_X4(kb[0], kb[1], kb[2], kb[3], ka0);
                unsigned int ka1 = (unsigned int)__cvta_generic_to_shared(
                    &Kb[(n0 + (lane & 7)) * QLDh + 32 + (lane >> 3) * 8]);
                LDM_X4(kb[4], kb[5], kb[6], kb[7], ka1);
#pragma unroll
                for (int kk = 0; kk < 4; kk++)
                    MMA16816(sacc[nt], qa[kk][0], qa[kk][1], qa[kk][2], qa[kk][3],
                             kb[2 * kk], kb[2 * kk + 1]);
            }

            // ---- softmax (registers) ----
            const bool domask = (jb * BK + BK - 1 > growbase);
            float mx0 = -1e30f, mx1 = -1e30f;
#pragma unroll
            for (int nt = 0; nt < 8; nt++) {
#pragma unroll
                for (int e = 0; e < 4; e++) {
                    float s = sacc[nt][e] * 0.125f;
                    if (domask) {
                        int gc = jb * BK + nt * 8 + ((lane & 3) << 1) + (e & 1);
                        int gr = grow0 + ((e >= 2) ? 8 : 0);
                        if (gc > gr) s = -1e30f;
                    }
                    sacc[nt][e] = s;
                    if (e < 2) mx0 = fmaxf(mx0, s); else mx1 = fmaxf(mx1, s);
                }
            }
            mx0 = fmaxf(mx0, __shfl_xor_sync(0xffffffffu, mx0, 1));
            mx0 = fmaxf(mx0, __shfl_xor_sync(0xffffffffu, mx0, 2));
            mx1 = fmaxf(mx1, __shfl_xor_sync(0xffffffffu, mx1, 1));
            mx1 = fmaxf(mx1, __shfl_xor_sync(0xffffffffu, mx1, 2));
            float nm0 = fmaxf(m0, mx0), nm1 = fmaxf(m1, mx1);
            float a0 = __expf(m0 - nm0), a1 = __expf(m1 - nm1);
            m0 = nm0; m1 = nm1;

            float sum0 = 0.f, sum1 = 0.f;
            uint32_t pa[4][4];
#pragma unroll
            for (int kk = 0; kk < 4; kk++) {
#pragma unroll
                for (int tt = 0; tt < 2; tt++) {
                    int nt = 2 * kk + tt;
                    float p0 = __expf(sacc[nt][0] - nm0);
                    float p1 = __expf(sacc[nt][1] - nm0);
                    float p2 = __expf(sacc[nt][2] - nm1);
                    float p3 = __expf(sacc[nt][3] - nm1);
                    sum0 += p0 + p1; sum1 += p2 + p3;
                    pa[kk][tt * 2 + 0] = pack_h2(p0, p1);
                    pa[kk][tt * 2 + 1] = pack_h2(p2, p3);
                }
            }
            sum0 += __shfl_xor_sync(0xffffffffu, sum0, 1);
            sum0 += __shfl_xor_sync(0xffffffffu, sum0, 2);
            sum1 += __shfl_xor_sync(0xffffffffu, sum1, 1);
            sum1 += __shfl_xor_sync(0xffffffffu, sum1, 2);
            l0 = l0 * a0 + sum0;
            l1 = l1 * a1 + sum1;

            // rescale O
#pragma unroll
            for (int nt = 0; nt < 8; nt++) {
                oacc[nt][0] *= a0; oacc[nt][1] *= a0;
                oacc[nt][2] *= a1; oacc[nt][3] *= a1;
            }

            // ---- O += P @ V ----
#pragma unroll
            for (int nt = 0; nt < 8; nt++) {
                const int n0 = nt * 8;
                uint32_t vb[8];
                unsigned int va0 = (unsigned int)__cvta_generic_to_shared(
                    &Vb[lane * QLDh + n0]);
                LDM_X4_T(vb[0], vb[1], vb[2], vb[3], va0);
                unsigned int va1 = (unsigned int)__cvta_generic_to_shared(
                    &Vb[(32 + lane) * QLDh + n0]);
                LDM_X4_T(vb[4], vb[5], vb[6], vb[7], va1);
#pragma unroll
                for (int kk = 0; kk < 4; kk++)
                    MMA16816(oacc[nt], pa[kk][0], pa[kk][1], pa[kk][2], pa[kk][3],
                             vb[2 * kk], vb[2 * kk + 1]);
            }
        }
        __syncthreads();
    }

    // ---- write O / l ----
    const float inv0 = 1.0f / l0;
    const float inv1 = 1.0f / l1;
    const int r0 = growbase + (lane >> 2);
    const size_t orow0 = (size_t)(b * kS + r0) * kD + h * kHD;
    const size_t orow1 = orow0 + 8 * kD;
#pragma unroll
    for (int nt = 0; nt < 8; nt++) {
        int c = nt * 8 + ((lane & 3) << 1);
        __half2 v0 = __floats2half2_rn(oacc[nt][0] * inv0, oacc[nt][1] * inv0);
        __half2 v1 = __floats2half2_rn(oacc[nt][2] * inv1, oacc[nt][3] * inv1);
        *reinterpret_cast<__half2*>(out + orow0 + c) = v0;
        *reinterpret_cast<__half2*>(out + orow1 + c) = v1;
    }
}

// ---------------- launch ----------------
extern "C" void kernel_launch(void* const* d_in, const int* in_sizes, int n_in,
                              void* d_out, int out_size)
{
    const float* x    = (const float*)d_in[0];
    const float* Wq   = (const float*)d_in[1];
    const float* bq   = (const float*)d_in[2];
    const float* Wk   = (const float*)d_in[3];
    const float* bk   = (const float*)d_in[4];
    const float* Wv   = (const float*)d_in[5];
    const float* bv   = (const float*)d_in[6];
    const float* Wo   = (const float*)d_in[7];
    const float* bo   = (const float*)d_in[8];
    const float* W1   = (const float*)d_in[9];
    const float* b1   = (const float*)d_in[10];
    const float* W2   = (const float*)d_in[11];
    const float* b2   = (const float*)d_in[12];
    const float* ln1g = (const float*)d_in[13];
    const float* ln1b = (const float*)d_in[14];
    const float* ln2g = (const float*)d_in[15];
    const float* ln2b = (const float*)d_in[16];
    float* out = (float*)d_out;

    __half *h1, *wqkv, *qkv, *attn, *ff1, *wo, *w1, *w2;
    float *bqkv, *x2;
    cudaGetSymbolAddress((void**)&h1,   g_h1);
    cudaGetSymbolAddress((void**)&wqkv, g_wqkv);
    cudaGetSymbolAddress((void**)&bqkv, g_bqkv);
    cudaGetSymbolAddress((void**)&qkv,  g_qkv);
    cudaGetSymbolAddress((void**)&attn, g_attn);
    cudaGetSymbolAddress((void**)&x2,   g_x2);
    cudaGetSymbolAddress((void**)&ff1,  g_ff1);
    cudaGetSymbolAddress((void**)&wo,   g_wo);
    cudaGetSymbolAddress((void**)&w1,   g_w1);
    cudaGetSymbolAddress((void**)&w2,   g_w2);

    cudaFuncSetAttribute(attn_kernel, cudaFuncAttributeMaxDynamicSharedMemorySize, ATT_SMEM);
    cudaFuncSetAttribute(gemm_h, cudaFuncAttributeMaxDynamicSharedMemorySize, GEMM_SMEM);

    tohalf_kernel<<<(kD * kD / 4 + 255) / 256, 256>>>(Wo, wo, kD * kD / 4);
    tohalf_kernel<<<(kD * kFF / 4 + 255) / 256, 256>>>(W1, w1, kD * kFF / 4);
    tohalf_kernel<<<(kFF * kD / 4 + 255) / 256, 256>>>(W2, w2, kFF * kD / 4);
    pack_qkv_kernel<<<(kD * kQKV + 255) / 256, 256>>>(Wq, Wk, Wv, bq, bk, bv);
    ln_kernel<<<kM, 256>>>(x, ln1g, ln1b, h1);
    gemm_h<<<dim3(kQKV / GBN, kM / GBM), 256, GEMM_SMEM>>>(h1, wqkv, nullptr, qkv, bqkv, nullptr,
                                                           kM, kQKV, kD, 0, 1);
    attn_kernel<<<dim3(kS / BQ, kB * kH), 256, ATT_SMEM>>>(qkv, attn);
    gemm_h<<<dim3(kD / GBN, kM / GBM), 256, GEMM_SMEM>>>(attn, wo, x2, nullptr, bo, x,
                                                         kM, kD, kD, 1, 0);
    ln_kernel<<<kM, 256>>>(x2, ln2g, ln2b, h1);
    gemm_h<<<dim3(kFF / GBN, kM / GBM), 256, GEMM_SMEM>>>(h1, w1, nullptr, ff1, b1, nullptr,
                                                          kM, kFF, kD, 2, 1);
    gemm_h<<<dim3(kD / GBN, kM / GBM), 256, GEMM_SMEM>>>(ff1, w2, out, nullptr, b2, x2,
                                                         kM, kD, kFF, 3, 0);
}